// round 8
// baseline (speedup 1.0000x reference)
#include <cuda_runtime.h>
#include <cuda_bf16.h>
#include <math.h>
#include <stdint.h>

// Problem constants: N=200000, K_IN=8, K_OUT=4, E=800000, D=64, H=128, O=1
#define MAX_N 200000
#define D_DIM 64
#define K_IN 8
#define K_OUT 4
#define H_DIM 128

__device__ float g_pooled[MAX_N * D_DIM];

// ---------------------------------------------------------------------------
// helpers
// ---------------------------------------------------------------------------
__device__ __forceinline__ uint32_t smem_u32(const void* p) {
    uint32_t a;
    asm("{ .reg .u64 t; cvta.to.shared.u64 t, %1; cvt.u32.u64 %0, t; }"
        : "=r"(a) : "l"(p));
    return a;
}

// pack two floats to bf16x2: lo -> bits[15:0], hi -> bits[31:16]
__device__ __forceinline__ uint32_t bf16x2_rn(float lo, float hi) {
    uint32_t r;
    asm("cvt.rn.bf16x2.f32 %0, %1, %2;" : "=r"(r) : "f"(hi), "f"(lo));
    return r;
}

// split 8 fp32 into hi-bf16 16B chunk + lo-bf16 16B chunk
__device__ __forceinline__ void split8(const float* f, uint4& hv, uint4& lv) {
    float hf[8], lf[8];
#pragma unroll
    for (int i = 0; i < 8; ++i) {
        __nv_bfloat16 hb = __float2bfloat16(f[i]);
        hf[i] = __bfloat162float(hb);
        lf[i] = f[i] - hf[i];
    }
    hv.x = bf16x2_rn(hf[0], hf[1]); hv.y = bf16x2_rn(hf[2], hf[3]);
    hv.z = bf16x2_rn(hf[4], hf[5]); hv.w = bf16x2_rn(hf[6], hf[7]);
    lv.x = bf16x2_rn(lf[0], lf[1]); lv.y = bf16x2_rn(lf[2], lf[3]);
    lv.z = bf16x2_rn(lf[4], lf[5]); lv.w = bf16x2_rn(lf[6], lf[7]);
}

#define LDMX4(r0, r1, r2, r3, addr) \
    asm volatile("ldmatrix.sync.aligned.m8n8.x4.shared.b16 {%0,%1,%2,%3}, [%4];" \
        : "=r"(r0), "=r"(r1), "=r"(r2), "=r"(r3) : "r"(addr))

#define MMA16816(c, a, b) \
    asm volatile("mma.sync.aligned.m16n8k16.row.col.f32.bf16.bf16.f32 " \
        "{%0,%1,%2,%3}, {%4,%5,%6,%7}, {%8,%9}, {%0,%1,%2,%3};" \
        : "+f"((c)[0]), "+f"((c)[1]), "+f"((c)[2]), "+f"((c)[3]) \
        : "r"((a)[0]), "r"((a)[1]), "r"((a)[2]), "r"((a)[3]), \
          "r"((b)[0]), "r"((b)[1]))

// ---------------------------------------------------------------------------
// Kernel 1: per-node attention + pooled context (unchanged)
// ---------------------------------------------------------------------------
__global__ void __launch_bounds__(256) attn_pool_kernel(
    const float* __restrict__ edges,
    const int* __restrict__ in_idx,
    const int* __restrict__ in_mask,
    int N)
{
    __shared__ float sE[8][K_IN * 68];

    const int lane = threadIdx.x & 31;
    const int w    = threadIdx.x >> 5;
    const int node = blockIdx.x * 8 + w;
    if (node >= N) return;

    float* sEw = &sE[w][0];

    int idx_l = 0, m_l = 0;
    if (lane < K_IN) {
        idx_l = in_idx[(size_t)node * K_IN + lane];
        m_l   = in_mask[(size_t)node * K_IN + lane];
    }

    float2 r[K_IN];
#pragma unroll
    for (int k = 0; k < K_IN; ++k) {
        int ek = __shfl_sync(0xffffffffu, idx_l, k);
        float2 v = *(const float2*)(edges + (size_t)ek * D_DIM + lane * 2);
        r[k] = v;
        *(float2*)(sEw + k * 68 + lane * 2) = v;
    }
    __syncwarp();

    const int q0 = lane >> 3;
    const int kk = lane & 7;
    const float4* Eq0 = (const float4*)(sEw + q0 * 68);
    const float4* Eq1 = (const float4*)(sEw + (q0 + 4) * 68);
    const float4* Ekp = (const float4*)(sEw + kk * 68);

    float s0 = 0.f, s1 = 0.f;
#pragma unroll
    for (int d4 = 0; d4 < 16; ++d4) {
        float4 b  = Ekp[d4];
        float4 a0 = Eq0[d4];
        float4 a1 = Eq1[d4];
        s0 += a0.x * b.x + a0.y * b.y + a0.z * b.z + a0.w * b.w;
        s1 += a1.x * b.x + a1.y * b.y + a1.z * b.z + a1.w * b.w;
    }
    s0 *= 0.125f;
    s1 *= 0.125f;

    int mk = __shfl_sync(0xffffffffu, m_l, kk);
    if (!mk) { s0 = -1e9f; s1 = -1e9f; }

    float mx0 = s0, mx1 = s1;
#pragma unroll
    for (int o = 1; o < 8; o <<= 1) {
        mx0 = fmaxf(mx0, __shfl_xor_sync(0xffffffffu, mx0, o));
        mx1 = fmaxf(mx1, __shfl_xor_sync(0xffffffffu, mx1, o));
    }
    float e0 = __expf(s0 - mx0);
    float e1 = __expf(s1 - mx1);
    float z0 = e0, z1 = e1;
#pragma unroll
    for (int o = 1; o < 8; o <<= 1) {
        z0 += __shfl_xor_sync(0xffffffffu, z0, o);
        z1 += __shfl_xor_sync(0xffffffffu, z1, o);
    }
    float a0 = e0 / z0;
    float a1 = e1 / z1;

    int mq0 = __shfl_sync(0xffffffffu, m_l, q0);
    int mq1 = __shfl_sync(0xffffffffu, m_l, q0 + 4);

    float v = (mq0 ? a0 : 0.f) + (mq1 ? a1 : 0.f);
    v += __shfl_xor_sync(0xffffffffu, v, 8);
    v += __shfl_xor_sync(0xffffffffu, v, 16);

    int cnt = m_l;
#pragma unroll
    for (int o = 1; o < 32; o <<= 1)
        cnt += __shfl_xor_sync(0xffffffffu, cnt, o);
    float inv_denom = 1.f / fmaxf((float)cnt, 1.f);

    float px = 0.f, py = 0.f;
#pragma unroll
    for (int k = 0; k < K_IN; ++k) {
        float wk = __shfl_sync(0xffffffffu, v, k);
        px += wk * r[k].x;
        py += wk * r[k].y;
    }
    float2 p2 = make_float2(px * inv_denom, py * inv_denom);
    *(float2*)(g_pooled + (size_t)node * D_DIM + lane * 2) = p2;
}

// ---------------------------------------------------------------------------
// Kernel 2: fused 3-layer MLP with HMMA, hi/lo split, fused 3-pass k-loop.
// CTA: 128 threads (4 warps), 64 rows. 2 CTAs/SM.
// Warp tile: 64m x 32n  (warp w covers n0 = w*32).
// SMEM byte layout (per CTA):
//   XHI@0      [64 m][128 k] bf16  (16 KB)    rows 256B, 16B-chunk XOR swizzle
//   XLO@16384  (16 KB)
//   WHI@32768  [128 h][128 k] bf16 (32 KB)
//   WLO@65536  (32 KB)
//   STG@98304  4 x 64 fp32 partials (1 KB)
// Per k-chunk per warp: 12 ldmatrix.x4 (Ahi x4, Alo x4, Bhi x2, Blo x2),
// 48 MMAs: acc += Ahi*Bhi + Ahi*Blo + Alo*Bhi.
// ---------------------------------------------------------------------------
#define XHI_B 0u
#define XLO_B 16384u
#define WHI_B 32768u
#define WLO_B 65536u
#define STG_B 98304u
#define MLP_SMEM_BYTES 99328

// byte offset inside a buffer for (row, 16B-chunk)
__device__ __forceinline__ uint32_t swz(int row, int chunk) {
    return (uint32_t)row * 256u + (uint32_t)((chunk ^ (row & 7)) << 4);
}

// fused 3-pass GEMM over k=128, warp tile 64m x 32n
__device__ __forceinline__ void gemm_fused(
    uint32_t XH, uint32_t XL, uint32_t WH, uint32_t WL,
    uint32_t aBase, uint32_t aKey, uint32_t cbA,
    uint32_t bOff0, uint32_t bOff1, uint32_t bKey, uint32_t cbB,
    float acc[4][4][4])
{
#pragma unroll
    for (int kc = 0; kc < 8; ++kc) {
        uint32_t ca = (uint32_t)((((uint32_t)(2 * kc) + cbA) ^ aKey) << 4);
        uint32_t cb = (uint32_t)((((uint32_t)(2 * kc) + cbB) ^ bKey) << 4);
        uint32_t ah[4][4], al[4][4];
        uint32_t bh0[4], bh1[4], bl0[4], bl1[4];
#pragma unroll
        for (int i = 0; i < 4; ++i) {
            LDMX4(ah[i][0], ah[i][1], ah[i][2], ah[i][3],
                  XH + aBase + (uint32_t)(i * 4096) + ca);
            LDMX4(al[i][0], al[i][1], al[i][2], al[i][3],
                  XL + aBase + (uint32_t)(i * 4096) + ca);
        }
        LDMX4(bh0[0], bh0[1], bh0[2], bh0[3], WH + bOff0 + cb);
        LDMX4(bh1[0], bh1[1], bh1[2], bh1[3], WH + bOff1 + cb);
        LDMX4(bl0[0], bl0[1], bl0[2], bl0[3], WL + bOff0 + cb);
        LDMX4(bl1[0], bl1[1], bl1[2], bl1[3], WL + bOff1 + cb);
#pragma unroll
        for (int i = 0; i < 4; ++i) {
            MMA16816(acc[i][0], ah[i], bh0 + 0);
            MMA16816(acc[i][1], ah[i], bh0 + 2);
            MMA16816(acc[i][2], ah[i], bh1 + 0);
            MMA16816(acc[i][3], ah[i], bh1 + 2);
        }
#pragma unroll
        for (int i = 0; i < 4; ++i) {
            MMA16816(acc[i][0], ah[i], bl0 + 0);
            MMA16816(acc[i][1], ah[i], bl0 + 2);
            MMA16816(acc[i][2], ah[i], bl1 + 0);
            MMA16816(acc[i][3], ah[i], bl1 + 2);
        }
#pragma unroll
        for (int i = 0; i < 4; ++i) {
            MMA16816(acc[i][0], al[i], bh0 + 0);
            MMA16816(acc[i][1], al[i], bh0 + 2);
            MMA16816(acc[i][2], al[i], bh1 + 0);
            MMA16816(acc[i][3], al[i], bh1 + 2);
        }
    }
}

// load weight matrix W [128][128] fp32 -> hi/lo bf16 buffers (swizzled)
// 128 threads: thread t handles full row h = t (16 chunks)
__device__ __forceinline__ void load_w_split(
    char* smem, uint32_t hi_off, uint32_t lo_off,
    const float* __restrict__ W, int t)
{
    const int h   = t & 127;
    const int key = h & 7;
    const float4* src = (const float4*)(W + (size_t)h * H_DIM);
#pragma unroll
    for (int c = 0; c < 16; ++c) {
        float4 f0 = src[2 * c], f1 = src[2 * c + 1];
        float f[8] = {f0.x, f0.y, f0.z, f0.w, f1.x, f1.y, f1.z, f1.w};
        uint4 hv, lv;
        split8(f, hv, lv);
        uint32_t off = (uint32_t)h * 256u + (uint32_t)((c ^ key) << 4);
        *(uint4*)(smem + hi_off + off) = hv;
        *(uint4*)(smem + lo_off + off) = lv;
    }
}

__global__ void __launch_bounds__(128, 2) mlp_kernel(
    const float* __restrict__ edges,
    const int* __restrict__ out_idx,
    const int* __restrict__ out_mask,
    const float* __restrict__ W0,
    const float* __restrict__ b0,
    const float* __restrict__ W1,
    const float* __restrict__ b1,
    const float* __restrict__ Wout,
    const float* __restrict__ bout,
    float* __restrict__ out)
{
    extern __shared__ char smem[];
    const uint32_t sb = smem_u32(smem);

    const int t    = threadIdx.x;
    const int lane = t & 31;
    const int w    = t >> 5;        // 0..3
    const int gid  = lane >> 2;     // 0..7
    const int tig  = lane & 3;      // 0..3
    const int n0   = w * 32;
    const long base = (long)blockIdx.x * 64;    // M = 800000 = 12500*64

    // ---- load X = [edges | pooled] -> hi/lo bf16 swizzled ----
    {
        const int row  = t & 63;
        const int half = t >> 6;    // 0: k 0..63 (edge), 1: k 64..127 (pooled)
        long grow = base + row;
        const float* src;
        if (half == 0) {
            int eidx = out_idx[grow];
            src = edges + (size_t)eidx * D_DIM;
        } else {
            src = g_pooled + (size_t)(grow >> 2) * D_DIM;
        }
        const float4* s4 = (const float4*)src;
        const int cbase = half * 8;
#pragma unroll
        for (int c = 0; c < 8; ++c) {
            float4 f0 = s4[2 * c], f1 = s4[2 * c + 1];
            float f[8] = {f0.x, f0.y, f0.z, f0.w, f1.x, f1.y, f1.z, f1.w};
            uint4 hv, lv;
            split8(f, hv, lv);
            uint32_t off = swz(row, cbase + c);
            *(uint4*)(smem + XHI_B + off) = hv;
            *(uint4*)(smem + XLO_B + off) = lv;
        }
    }
    load_w_split(smem, WHI_B, WLO_B, W0, t);
    __syncthreads();

    // ---- per-lane ldmatrix geometry ----
    const int sub = lane >> 3;      // 0..3 (matrix slot)
    const int r8  = lane & 7;
    // A: row within 16-block = (sub&1)*8 + r8; block i adds 16i (4096B)
    const uint32_t aBase = (uint32_t)((sub & 1) * 8 + r8) * 256u;
    const uint32_t aKey  = (uint32_t)r8;
    const uint32_t cbA   = (uint32_t)(sub >> 1);
    // B: j=0 tile rows n0 + (sub>>1)*8 + r8 ; j=1 adds 16
    const int bRow = n0 + (sub >> 1) * 8 + r8;
    const uint32_t bOff0 = (uint32_t)bRow * 256u;
    const uint32_t bOff1 = (uint32_t)(bRow + 16) * 256u;
    const uint32_t bKey  = (uint32_t)r8;
    const uint32_t cbB   = (uint32_t)(sub & 1);

    const uint32_t XH = sb + XHI_B, XL = sb + XLO_B;
    const uint32_t WH = sb + WHI_B, WL = sb + WLO_B;

    // ---- GEMM layer 1 ----
    float acc[4][4][4];
#pragma unroll
    for (int i = 0; i < 4; ++i)
#pragma unroll
        for (int j = 0; j < 4; ++j)
#pragma unroll
            for (int p = 0; p < 4; ++p) acc[i][j][p] = 0.f;

    gemm_fused(XH, XL, WH, WL, aBase, aKey, cbA, bOff0, bOff1, bKey, cbB, acc);

    __syncthreads();   // all reads of X/W done

    // ---- epilogue 1: H = relu(acc + b0) -> X buffers (bf16 hi/lo) ----
#pragma unroll
    for (int j = 0; j < 4; ++j) {
        int h0 = n0 + 8 * j + 2 * tig;
        float2 bb = *(const float2*)(b0 + h0);
        int chunk = (n0 + 8 * j) >> 3;
        uint32_t cof = (uint32_t)(tig * 4);
#pragma unroll
        for (int i = 0; i < 4; ++i) {
#pragma unroll
            for (int rs = 0; rs < 2; ++rs) {
                int row = 16 * i + 8 * rs + gid;
                float v0 = fmaxf(acc[i][j][2 * rs]     + bb.x, 0.f);
                float v1 = fmaxf(acc[i][j][2 * rs + 1] + bb.y, 0.f);
                __nv_bfloat16 h0b = __float2bfloat16(v0);
                __nv_bfloat16 h1b = __float2bfloat16(v1);
                float l0 = v0 - __bfloat162float(h0b);
                float l1 = v1 - __bfloat162float(h1b);
                uint32_t hw = bf16x2_rn(__bfloat162float(h0b), __bfloat162float(h1b));
                uint32_t lw = bf16x2_rn(l0, l1);
                uint32_t off = (uint32_t)row * 256u
                             + (uint32_t)((chunk ^ (row & 7)) << 4) + cof;
                *(uint32_t*)(smem + XHI_B + off) = hw;
                *(uint32_t*)(smem + XLO_B + off) = lw;
            }
        }
    }
    load_w_split(smem, WHI_B, WLO_B, W1, t);
    __syncthreads();

    // ---- GEMM layer 2 ----
#pragma unroll
    for (int i = 0; i < 4; ++i)
#pragma unroll
        for (int j = 0; j < 4; ++j)
#pragma unroll
            for (int p = 0; p < 4; ++p) acc[i][j][p] = 0.f;

    gemm_fused(XH, XL, WH, WL, aBase, aKey, cbA, bOff0, bOff1, bKey, cbB, acc);

    // ---- final epilogue: relu(+b1), dot Wout, reduce ----
    float y[4][2];
#pragma unroll
    for (int i = 0; i < 4; ++i) { y[i][0] = 0.f; y[i][1] = 0.f; }
#pragma unroll
    for (int j = 0; j < 4; ++j) {
        int h0 = n0 + 8 * j + 2 * tig;
        float2 bb = *(const float2*)(b1 + h0);
        float2 ww = *(const float2*)(Wout + h0);
#pragma unroll
        for (int i = 0; i < 4; ++i) {
#pragma unroll
            for (int rs = 0; rs < 2; ++rs) {
                float v0 = fmaxf(acc[i][j][2 * rs]     + bb.x, 0.f);
                float v1 = fmaxf(acc[i][j][2 * rs + 1] + bb.y, 0.f);
                y[i][rs] += ww.x * v0 + ww.y * v1;
            }
        }
    }
    // reduce over tig lanes (bits 0,1)
#pragma unroll
    for (int i = 0; i < 4; ++i)
#pragma unroll
        for (int rs = 0; rs < 2; ++rs) {
            y[i][rs] += __shfl_xor_sync(0xffffffffu, y[i][rs], 1);
            y[i][rs] += __shfl_xor_sync(0xffffffffu, y[i][rs], 2);
        }

    // stage partials: 4 n-warp-columns x 64 m
    float* stage = (float*)(smem + STG_B);
    if (tig == 0) {
#pragma unroll
        for (int i = 0; i < 4; ++i)
#pragma unroll
            for (int rs = 0; rs < 2; ++rs) {
                int row = 16 * i + 8 * rs + gid;
                stage[w * 64 + row] = y[i][rs];
            }
    }
    __syncthreads();

    if (t < 64) {
        long row = base + t;
        float s = stage[t] + stage[64 + t] + stage[128 + t] + stage[192 + t]
                + bout[0];
        out[row] = s * (float)out_mask[row];
    }
}

// ---------------------------------------------------------------------------
extern "C" void kernel_launch(void* const* d_in, const int* in_sizes, int n_in,
                              void* d_out, int out_size) {
    const float* edges   = (const float*)d_in[0];
    const int*   in_idx  = (const int*)d_in[1];
    const int*   in_mask = (const int*)d_in[2];
    const int*   out_idx = (const int*)d_in[3];
    const int*   out_mask= (const int*)d_in[4];
    const float* W0      = (const float*)d_in[5];
    const float* b0      = (const float*)d_in[6];
    const float* W1      = (const float*)d_in[7];
    const float* b1      = (const float*)d_in[8];
    const float* Wout    = (const float*)d_in[9];
    const float* bout    = (const float*)d_in[10];
    float* out = (float*)d_out;

    int N = in_sizes[1] / K_IN;     // 200000
    int M = N * K_OUT;              // 800000 = 12500 * 64

    attn_pool_kernel<<<(N + 7) / 8, 256>>>(edges, in_idx, in_mask, N);

    cudaFuncSetAttribute(mlp_kernel,
                         cudaFuncAttributeMaxDynamicSharedMemorySize,
                         MLP_SMEM_BYTES);
    mlp_kernel<<<M / 64, 128, MLP_SMEM_BYTES>>>(
        edges, out_idx, out_mask, W0, b0, W1, b1, Wout, bout, out);
}

// round 9
// speedup vs baseline: 1.2612x; 1.2612x over previous
#include <cuda_runtime.h>
#include <cuda_bf16.h>
#include <math.h>
#include <stdint.h>

// Problem constants: N=200000, K_IN=8, K_OUT=4, E=800000, D=64, H=128, O=1
#define D_DIM 64
#define K_IN 8
#define K_OUT 4
#define H_DIM 128
#define N_TILES 6250        // 800000 rows / 128 rows per tile
#define GRID_CTAS 148

// ---------------------------------------------------------------------------
// helpers
// ---------------------------------------------------------------------------
__device__ __forceinline__ uint32_t smem_u32(const void* p) {
    uint32_t a;
    asm("{ .reg .u64 t; cvta.to.shared.u64 t, %1; cvt.u32.u64 %0, t; }"
        : "=r"(a) : "l"(p));
    return a;
}

// pack two floats to bf16x2: lo -> bits[15:0], hi -> bits[31:16]
__device__ __forceinline__ uint32_t bf16x2_rn(float lo, float hi) {
    uint32_t r;
    asm("cvt.rn.bf16x2.f32 %0, %1, %2;" : "=r"(r) : "f"(hi), "f"(lo));
    return r;
}

// split 8 fp32 into hi-bf16 16B chunk + lo-bf16 16B chunk
__device__ __forceinline__ void split8(const float* f, uint4& hv, uint4& lv) {
    float hf[8], lf[8];
#pragma unroll
    for (int i = 0; i < 8; ++i) {
        __nv_bfloat16 hb = __float2bfloat16(f[i]);
        hf[i] = __bfloat162float(hb);
        lf[i] = f[i] - hf[i];
    }
    hv.x = bf16x2_rn(hf[0], hf[1]); hv.y = bf16x2_rn(hf[2], hf[3]);
    hv.z = bf16x2_rn(hf[4], hf[5]); hv.w = bf16x2_rn(hf[6], hf[7]);
    lv.x = bf16x2_rn(lf[0], lf[1]); lv.y = bf16x2_rn(lf[2], lf[3]);
    lv.z = bf16x2_rn(lf[4], lf[5]); lv.w = bf16x2_rn(lf[6], lf[7]);
}

#define LDMX4(r0, r1, r2, r3, addr) \
    asm volatile("ldmatrix.sync.aligned.m8n8.x4.shared.b16 {%0,%1,%2,%3}, [%4];" \
        : "=r"(r0), "=r"(r1), "=r"(r2), "=r"(r3) : "r"(addr))

#define MMA16816(c, a, b) \
    asm volatile("mma.sync.aligned.m16n8k16.row.col.f32.bf16.bf16.f32 " \
        "{%0,%1,%2,%3}, {%4,%5,%6,%7}, {%8,%9}, {%0,%1,%2,%3};" \
        : "+f"((c)[0]), "+f"((c)[1]), "+f"((c)[2]), "+f"((c)[3]) \
        : "r"((a)[0]), "r"((a)[1]), "r"((a)[2]), "r"((a)[3]), \
          "r"((b)[0]), "r"((b)[1]))

// ---------------------------------------------------------------------------
// SMEM layout (bytes), one persistent CTA per SM:
//   XHI @ 0        [128 m][128 k] bf16 hi   (32 KB)  256B rows, XOR-16B swizzle
//   XLO @ 32768    (32 KB)
//   W0HI@ 65536    [128 h][128 k] bf16 hi   (32 KB)
//   W0LO@ 98304    (32 KB)
//   W1HI@ 131072   (32 KB)
//   W1LO@ 163840   (32 KB)
//   PS  @ 196608   32 nodes x 64 fp32 pooled scratch (8 KB)
//   STG @ 204800   4 x 128 fp32 partials (2 KB)
// Total 206848. Attention staging reuses bytes [0, 34816) of the X region.
// ---------------------------------------------------------------------------
#define XHI_B   0u
#define XLO_B   32768u
#define W0HI_B  65536u
#define W0LO_B  98304u
#define W1HI_B  131072u
#define W1LO_B  163840u
#define PS_B    196608u
#define STG_B   204800u
#define SMEM_TOTAL 206848

__device__ __forceinline__ uint32_t swz(int row, int chunk) {
    return (uint32_t)row * 256u + (uint32_t)((chunk ^ (row & 7)) << 4);
}

// fused 3-pass GEMM over k=128, warp tile 32m x 32n (R7 core)
__device__ __forceinline__ void gemm_fused(
    uint32_t XH, uint32_t XL, uint32_t WH, uint32_t WL,
    uint32_t aOff0, uint32_t aOff1, uint32_t aKey, uint32_t cbA,
    uint32_t bOff0, uint32_t bOff1, uint32_t bKey, uint32_t cbB,
    float acc[2][4][4])
{
#pragma unroll
    for (int kc = 0; kc < 8; ++kc) {
        uint32_t ca = (uint32_t)((((uint32_t)(2 * kc) + cbA) ^ aKey) << 4);
        uint32_t cb = (uint32_t)((((uint32_t)(2 * kc) + cbB) ^ bKey) << 4);
        uint32_t ah0[4], ah1[4], al0[4], al1[4];
        uint32_t bh0[4], bh1[4], bl0[4], bl1[4];
        LDMX4(ah0[0], ah0[1], ah0[2], ah0[3], XH + aOff0 + ca);
        LDMX4(ah1[0], ah1[1], ah1[2], ah1[3], XH + aOff1 + ca);
        LDMX4(bh0[0], bh0[1], bh0[2], bh0[3], WH + bOff0 + cb);
        LDMX4(bh1[0], bh1[1], bh1[2], bh1[3], WH + bOff1 + cb);
        LDMX4(al0[0], al0[1], al0[2], al0[3], XL + aOff0 + ca);
        LDMX4(al1[0], al1[1], al1[2], al1[3], XL + aOff1 + ca);
        LDMX4(bl0[0], bl0[1], bl0[2], bl0[3], WL + bOff0 + cb);
        LDMX4(bl1[0], bl1[1], bl1[2], bl1[3], WL + bOff1 + cb);
        MMA16816(acc[0][0], ah0, bh0 + 0);
        MMA16816(acc[0][1], ah0, bh0 + 2);
        MMA16816(acc[0][2], ah0, bh1 + 0);
        MMA16816(acc[0][3], ah0, bh1 + 2);
        MMA16816(acc[1][0], ah1, bh0 + 0);
        MMA16816(acc[1][1], ah1, bh0 + 2);
        MMA16816(acc[1][2], ah1, bh1 + 0);
        MMA16816(acc[1][3], ah1, bh1 + 2);
        MMA16816(acc[0][0], ah0, bl0 + 0);
        MMA16816(acc[0][1], ah0, bl0 + 2);
        MMA16816(acc[0][2], ah0, bl1 + 0);
        MMA16816(acc[0][3], ah0, bl1 + 2);
        MMA16816(acc[1][0], ah1, bl0 + 0);
        MMA16816(acc[1][1], ah1, bl0 + 2);
        MMA16816(acc[1][2], ah1, bl1 + 0);
        MMA16816(acc[1][3], ah1, bl1 + 2);
        MMA16816(acc[0][0], al0, bh0 + 0);
        MMA16816(acc[0][1], al0, bh0 + 2);
        MMA16816(acc[0][2], al0, bh1 + 0);
        MMA16816(acc[0][3], al0, bh1 + 2);
        MMA16816(acc[1][0], al1, bh0 + 0);
        MMA16816(acc[1][1], al1, bh0 + 2);
        MMA16816(acc[1][2], al1, bh1 + 0);
        MMA16816(acc[1][3], al1, bh1 + 2);
    }
}

// ---------------------------------------------------------------------------
// Persistent fused kernel: attention + pooled + 3-layer MLP per 128-row tile.
// 148 CTAs x 512 threads (16 warps), ~42 tiles each.
// ---------------------------------------------------------------------------
__global__ void __launch_bounds__(512, 1) fused_kernel(
    const float* __restrict__ edges,
    const int* __restrict__ in_idx,
    const int* __restrict__ in_mask,
    const int* __restrict__ out_idx,
    const int* __restrict__ out_mask,
    const float* __restrict__ W0,
    const float* __restrict__ b0,
    const float* __restrict__ W1,
    const float* __restrict__ b1,
    const float* __restrict__ Wout,
    const float* __restrict__ bout,
    float* __restrict__ out)
{
    extern __shared__ char smem[];
    const uint32_t sb = smem_u32(smem);

    const int t    = threadIdx.x;
    const int lane = t & 31;
    const int w    = t >> 5;        // 0..15

    // ---- load W0/W1 -> hi/lo bf16 smem, ONCE ----
    {
        const int h = t & 127;
        const int q = t >> 7;       // 0..3, 4 chunks each
        const int key = h & 7;
        const float4* s0 = (const float4*)(W0 + (size_t)h * H_DIM + q * 32);
        const float4* s1 = (const float4*)(W1 + (size_t)h * H_DIM + q * 32);
#pragma unroll
        for (int c = 0; c < 4; ++c) {
            int chunk = q * 4 + c;
            uint32_t off = (uint32_t)h * 256u + (uint32_t)((chunk ^ key) << 4);
            {
                float4 f0 = s0[2 * c], f1 = s0[2 * c + 1];
                float f[8] = {f0.x, f0.y, f0.z, f0.w, f1.x, f1.y, f1.z, f1.w};
                uint4 hv, lv;
                split8(f, hv, lv);
                *(uint4*)(smem + W0HI_B + off) = hv;
                *(uint4*)(smem + W0LO_B + off) = lv;
            }
            {
                float4 f0 = s1[2 * c], f1 = s1[2 * c + 1];
                float f[8] = {f0.x, f0.y, f0.z, f0.w, f1.x, f1.y, f1.z, f1.w};
                uint4 hv, lv;
                split8(f, hv, lv);
                *(uint4*)(smem + W1HI_B + off) = hv;
                *(uint4*)(smem + W1LO_B + off) = lv;
            }
        }
    }
    // (visibility covered by the first __syncthreads below)

    // ---- per-lane GEMM geometry (warp tile 32m x 32n) ----
    const int m0  = (w & 3) * 32;
    const int n0  = (w >> 2) * 32;
    const int gid = lane >> 2;      // 0..7
    const int tig = lane & 3;       // 0..3
    const int sub = lane >> 3;      // 0..3
    const int r8  = lane & 7;
    const int aRow = m0 + (sub & 1) * 8 + r8;
    const uint32_t aOff0 = (uint32_t)aRow * 256u;
    const uint32_t aOff1 = (uint32_t)(aRow + 16) * 256u;
    const uint32_t aKey  = (uint32_t)r8;
    const uint32_t cbA   = (uint32_t)(sub >> 1);
    const int bRow = n0 + (sub >> 1) * 8 + r8;
    const uint32_t bOff0 = (uint32_t)bRow * 256u;
    const uint32_t bOff1 = (uint32_t)(bRow + 16) * 256u;
    const uint32_t bKey  = (uint32_t)r8;
    const uint32_t cbB   = (uint32_t)(sub & 1);

    const uint32_t XH = sb + XHI_B, XL = sb + XLO_B;

    float* PSf = (float*)(smem + PS_B);
    float* stage = (float*)(smem + STG_B);
    float* sEw = (float*)(smem + (size_t)w * 2176);  // attn staging in X region

    for (int tile = blockIdx.x; tile < N_TILES; tile += gridDim.x) {
        const long base = (long)tile * 128;

        // ============ attention: 2 nodes per warp -> PS ============
#pragma unroll 1
        for (int ns = 0; ns < 2; ++ns) {
            const int node = tile * 32 + w * 2 + ns;

            int idx_l = 0, m_l = 0;
            if (lane < K_IN) {
                idx_l = in_idx[(size_t)node * K_IN + lane];
                m_l   = in_mask[(size_t)node * K_IN + lane];
            }

            float2 r[K_IN];
#pragma unroll
            for (int k = 0; k < K_IN; ++k) {
                int ek = __shfl_sync(0xffffffffu, idx_l, k);
                float2 v = *(const float2*)(edges + (size_t)ek * D_DIM + lane * 2);
                r[k] = v;
                *(float2*)(sEw + k * 68 + lane * 2) = v;
            }
            __syncwarp();

            const int q0 = lane >> 3;
            const int kk = lane & 7;
            const float4* Eq0 = (const float4*)(sEw + q0 * 68);
            const float4* Eq1 = (const float4*)(sEw + (q0 + 4) * 68);
            const float4* Ekp = (const float4*)(sEw + kk * 68);

            float s0 = 0.f, s1 = 0.f;
#pragma unroll
            for (int d4 = 0; d4 < 16; ++d4) {
                float4 b  = Ekp[d4];
                float4 a0 = Eq0[d4];
                float4 a1 = Eq1[d4];
                s0 += a0.x * b.x + a0.y * b.y + a0.z * b.z + a0.w * b.w;
                s1 += a1.x * b.x + a1.y * b.y + a1.z * b.z + a1.w * b.w;
            }
            s0 *= 0.125f;
            s1 *= 0.125f;

            int mk = __shfl_sync(0xffffffffu, m_l, kk);
            if (!mk) { s0 = -1e9f; s1 = -1e9f; }

            float mx0 = s0, mx1 = s1;
#pragma unroll
            for (int o = 1; o < 8; o <<= 1) {
                mx0 = fmaxf(mx0, __shfl_xor_sync(0xffffffffu, mx0, o));
                mx1 = fmaxf(mx1, __shfl_xor_sync(0xffffffffu, mx1, o));
            }
            float e0 = __expf(s0 - mx0);
            float e1 = __expf(s1 - mx1);
            float z0 = e0, z1 = e1;
#pragma unroll
            for (int o = 1; o < 8; o <<= 1) {
                z0 += __shfl_xor_sync(0xffffffffu, z0, o);
                z1 += __shfl_xor_sync(0xffffffffu, z1, o);
            }
            float a0 = e0 / z0;
            float a1 = e1 / z1;

            int mq0 = __shfl_sync(0xffffffffu, m_l, q0);
            int mq1 = __shfl_sync(0xffffffffu, m_l, q0 + 4);

            float v = (mq0 ? a0 : 0.f) + (mq1 ? a1 : 0.f);
            v += __shfl_xor_sync(0xffffffffu, v, 8);
            v += __shfl_xor_sync(0xffffffffu, v, 16);

            int cnt = m_l;
#pragma unroll
            for (int o = 1; o < 32; o <<= 1)
                cnt += __shfl_xor_sync(0xffffffffu, cnt, o);
            float inv_denom = 1.f / fmaxf((float)cnt, 1.f);

            float px = 0.f, py = 0.f;
#pragma unroll
            for (int k = 0; k < K_IN; ++k) {
                float wk = __shfl_sync(0xffffffffu, v, k);
                px += wk * r[k].x;
                py += wk * r[k].y;
            }
            *(float2*)(PSf + (size_t)(w * 2 + ns) * D_DIM + lane * 2) =
                make_float2(px * inv_denom, py * inv_denom);
        }
        __syncthreads();   // PS ready; attn staging reads done; W visible

        // ============ X fill: [edge | pooled] -> hi/lo bf16 ============
        {
            const int row = t & 127;
            const int q   = t >> 7;      // 0..3, 4 chunks (32 values) each
            long grow = base + row;
            const float* src;
            if (q < 2) {
                int eidx = out_idx[grow];
                src = edges + (size_t)eidx * D_DIM + q * 32;
            } else {
                src = PSf + (size_t)(row >> 2) * D_DIM + (q - 2) * 32;
            }
            const float4* s4 = (const float4*)src;
            const int cbase = q * 4;
#pragma unroll
            for (int c = 0; c < 4; ++c) {
                float4 f0 = s4[2 * c], f1 = s4[2 * c + 1];
                float f[8] = {f0.x, f0.y, f0.z, f0.w, f1.x, f1.y, f1.z, f1.w};
                uint4 hv, lv;
                split8(f, hv, lv);
                uint32_t off = swz(row, cbase + c);
                *(uint4*)(smem + XHI_B + off) = hv;
                *(uint4*)(smem + XLO_B + off) = lv;
            }
        }
        __syncthreads();

        // ============ GEMM layer 1 ============
        float acc[2][4][4];
#pragma unroll
        for (int i = 0; i < 2; ++i)
#pragma unroll
            for (int j = 0; j < 4; ++j)
#pragma unroll
                for (int p = 0; p < 4; ++p) acc[i][j][p] = 0.f;

        gemm_fused(XH, XL, sb + W0HI_B, sb + W0LO_B,
                   aOff0, aOff1, aKey, cbA, bOff0, bOff1, bKey, cbB, acc);

        __syncthreads();   // all reads of X done before epilogue overwrites

        // ---- epilogue 1: H = relu(acc + b0) -> X buffers ----
#pragma unroll
        for (int j = 0; j < 4; ++j) {
            int h0 = n0 + 8 * j + 2 * tig;
            float2 bb = *(const float2*)(b0 + h0);
            int chunk = (n0 + 8 * j) >> 3;
            uint32_t cof = (uint32_t)(tig * 4);
#pragma unroll
            for (int i = 0; i < 2; ++i) {
#pragma unroll
                for (int rs = 0; rs < 2; ++rs) {
                    int row = m0 + 16 * i + 8 * rs + gid;
                    float v0 = fmaxf(acc[i][j][2 * rs]     + bb.x, 0.f);
                    float v1 = fmaxf(acc[i][j][2 * rs + 1] + bb.y, 0.f);
                    __nv_bfloat16 h0b = __float2bfloat16(v0);
                    __nv_bfloat16 h1b = __float2bfloat16(v1);
                    float l0 = v0 - __bfloat162float(h0b);
                    float l1 = v1 - __bfloat162float(h1b);
                    uint32_t hw = bf16x2_rn(__bfloat162float(h0b),
                                            __bfloat162float(h1b));
                    uint32_t lw = bf16x2_rn(l0, l1);
                    uint32_t off = (uint32_t)row * 256u
                                 + (uint32_t)((chunk ^ (row & 7)) << 4) + cof;
                    *(uint32_t*)(smem + XHI_B + off) = hw;
                    *(uint32_t*)(smem + XLO_B + off) = lw;
                }
            }
        }
        __syncthreads();

        // ============ GEMM layer 2 ============
#pragma unroll
        for (int i = 0; i < 2; ++i)
#pragma unroll
            for (int j = 0; j < 4; ++j)
#pragma unroll
                for (int p = 0; p < 4; ++p) acc[i][j][p] = 0.f;

        gemm_fused(XH, XL, sb + W1HI_B, sb + W1LO_B,
                   aOff0, aOff1, aKey, cbA, bOff0, bOff1, bKey, cbB, acc);

        // ---- final epilogue: relu(+b1), dot Wout, reduce ----
        float y[2][2] = {{0.f, 0.f}, {0.f, 0.f}};
#pragma unroll
        for (int j = 0; j < 4; ++j) {
            int h0 = n0 + 8 * j + 2 * tig;
            float2 bb = *(const float2*)(b1 + h0);
            float2 ww = *(const float2*)(Wout + h0);
#pragma unroll
            for (int i = 0; i < 2; ++i) {
#pragma unroll
                for (int rs = 0; rs < 2; ++rs) {
                    float v0 = fmaxf(acc[i][j][2 * rs]     + bb.x, 0.f);
                    float v1 = fmaxf(acc[i][j][2 * rs + 1] + bb.y, 0.f);
                    y[i][rs] += ww.x * v0 + ww.y * v1;
                }
            }
        }
#pragma unroll
        for (int i = 0; i < 2; ++i)
#pragma unroll
            for (int rs = 0; rs < 2; ++rs) {
                y[i][rs] += __shfl_xor_sync(0xffffffffu, y[i][rs], 1);
                y[i][rs] += __shfl_xor_sync(0xffffffffu, y[i][rs], 2);
            }

        if (tig == 0) {
            int col = w >> 2;
#pragma unroll
            for (int i = 0; i < 2; ++i)
#pragma unroll
                for (int rs = 0; rs < 2; ++rs) {
                    int row = m0 + 16 * i + 8 * rs + gid;
                    stage[col * 128 + row] = y[i][rs];
                }
        }
        __syncthreads();   // stage ready; also GEMM2 X-reads complete

        if (t < 128) {
            long row = base + t;
            float s = stage[t] + stage[128 + t] + stage[256 + t]
                    + stage[384 + t] + bout[0];
            out[row] = s * (float)out_mask[row];
        }
        // next tile's attention overwrites X staging + PS; the __syncthreads
        // above guarantees all GEMM2 reads and stage reads are ordered before
        // those writes for every thread except the out-writers, whose stage
        // reads target a disjoint smem region from attn's X/PS writes.
        __syncthreads();
    }
}

// ---------------------------------------------------------------------------
extern "C" void kernel_launch(void* const* d_in, const int* in_sizes, int n_in,
                              void* d_out, int out_size) {
    const float* edges   = (const float*)d_in[0];
    const int*   in_idx  = (const int*)d_in[1];
    const int*   in_mask = (const int*)d_in[2];
    const int*   out_idx = (const int*)d_in[3];
    const int*   out_mask= (const int*)d_in[4];
    const float* W0      = (const float*)d_in[5];
    const float* b0      = (const float*)d_in[6];
    const float* W1      = (const float*)d_in[7];
    const float* b1      = (const float*)d_in[8];
    const float* Wout    = (const float*)d_in[9];
    const float* bout    = (const float*)d_in[10];
    float* out = (float*)d_out;

    cudaFuncSetAttribute(fused_kernel,
                         cudaFuncAttributeMaxDynamicSharedMemorySize,
                         SMEM_TOTAL);
    fused_kernel<<<GRID_CTAS, 512, SMEM_TOTAL>>>(
        edges, in_idx, in_mask, out_idx, out_mask,
        W0, b0, W1, b1, Wout, bout, out);
}

// round 10
// speedup vs baseline: 1.4931x; 1.1839x over previous
#include <cuda_runtime.h>
#include <cuda_bf16.h>
#include <cuda_fp16.h>
#include <math.h>
#include <stdint.h>

// Problem constants: N=200000, K_IN=8, K_OUT=4, E=800000, D=64, H=128, O=1
#define D_DIM 64
#define K_IN 8
#define K_OUT 4
#define H_DIM 128
#define N_TILES 6250        // 800000 rows / 128 rows per tile
#define GRID_CTAS 148

// ---------------------------------------------------------------------------
// helpers
// ---------------------------------------------------------------------------
__device__ __forceinline__ uint32_t smem_u32(const void* p) {
    uint32_t a;
    asm("{ .reg .u64 t; cvta.to.shared.u64 t, %1; cvt.u32.u64 %0, t; }"
        : "=r"(a) : "l"(p));
    return a;
}

// pack two floats to f16x2: lo -> bits[15:0], hi -> bits[31:16]
__device__ __forceinline__ uint32_t f16x2_rn(float lo, float hi) {
    uint32_t r;
    asm("cvt.rn.f16x2.f32 %0, %1, %2;" : "=r"(r) : "f"(hi), "f"(lo));
    return r;
}

// split 8 fp32 into hi-fp16 16B chunk + lo-fp16 16B chunk
__device__ __forceinline__ void split8h(const float* f, uint4& hv, uint4& lv) {
    float hf[8], lf[8];
#pragma unroll
    for (int i = 0; i < 8; ++i) {
        __half hb = __float2half_rn(f[i]);
        hf[i] = __half2float(hb);
        lf[i] = f[i] - hf[i];
    }
    hv.x = f16x2_rn(hf[0], hf[1]); hv.y = f16x2_rn(hf[2], hf[3]);
    hv.z = f16x2_rn(hf[4], hf[5]); hv.w = f16x2_rn(hf[6], hf[7]);
    lv.x = f16x2_rn(lf[0], lf[1]); lv.y = f16x2_rn(lf[2], lf[3]);
    lv.z = f16x2_rn(lf[4], lf[5]); lv.w = f16x2_rn(lf[6], lf[7]);
}

// convert 8 fp32 to single fp16 16B chunk
__device__ __forceinline__ uint4 cvt8h(const float* f) {
    uint4 v;
    v.x = f16x2_rn(f[0], f[1]); v.y = f16x2_rn(f[2], f[3]);
    v.z = f16x2_rn(f[4], f[5]); v.w = f16x2_rn(f[6], f[7]);
    return v;
}

#define LDMX4(r0, r1, r2, r3, addr) \
    asm volatile("ldmatrix.sync.aligned.m8n8.x4.shared.b16 {%0,%1,%2,%3}, [%4];" \
        : "=r"(r0), "=r"(r1), "=r"(r2), "=r"(r3) : "r"(addr))

#define MMAF16(c, a, b) \
    asm volatile("mma.sync.aligned.m16n8k16.row.col.f32.f16.f16.f32 " \
        "{%0,%1,%2,%3}, {%4,%5,%6,%7}, {%8,%9}, {%0,%1,%2,%3};" \
        : "+f"((c)[0]), "+f"((c)[1]), "+f"((c)[2]), "+f"((c)[3]) \
        : "r"((a)[0]), "r"((a)[1]), "r"((a)[2]), "r"((a)[3]), \
          "r"((b)[0]), "r"((b)[1]))

// ---------------------------------------------------------------------------
// SMEM layout (bytes), one persistent CTA per SM:
//   XHI @ 0        [128 m][128 k] fp16 hi   (32 KB)  256B rows, XOR-16B swizzle
//   XLO @ 32768    (32 KB)
//   W0  @ 65536    [128 h][128 k] fp16      (32 KB)
//   W1  @ 98304    (32 KB)
//   ATT @ 131072   16 warps x 2176 B attention staging (34816 B)
//   PS  @ 165888   32 nodes x 64 fp32 pooled scratch (8 KB)
//   STG @ 174080   4 x 128 fp32 partials (2 KB)
// Total 176128 bytes.
// ---------------------------------------------------------------------------
#define XHI_B   0u
#define XLO_B   32768u
#define W0_B    65536u
#define W1_B    98304u
#define ATT_B   131072u
#define PS_B    165888u
#define STG_B   174080u
#define SMEM_TOTAL 176128

__device__ __forceinline__ uint32_t swz(int row, int chunk) {
    return (uint32_t)row * 256u + (uint32_t)((chunk ^ (row & 7)) << 4);
}

// fused 2-pass GEMM over k=128, warp tile 32m x 32n:
//   acc += Ahi*W + Alo*W      (A fp16 hi/lo split, W single fp16)
__device__ __forceinline__ void gemm_fused(
    uint32_t XH, uint32_t XL, uint32_t WB,
    uint32_t aOff0, uint32_t aOff1, uint32_t aKey, uint32_t cbA,
    uint32_t bOff0, uint32_t bOff1, uint32_t bKey, uint32_t cbB,
    float acc[2][4][4])
{
#pragma unroll
    for (int kc = 0; kc < 8; ++kc) {
        uint32_t ca = (uint32_t)((((uint32_t)(2 * kc) + cbA) ^ aKey) << 4);
        uint32_t cb = (uint32_t)((((uint32_t)(2 * kc) + cbB) ^ bKey) << 4);
        uint32_t ah0[4], ah1[4], al0[4], al1[4];
        uint32_t bq0[4], bq1[4];
        LDMX4(ah0[0], ah0[1], ah0[2], ah0[3], XH + aOff0 + ca);
        LDMX4(ah1[0], ah1[1], ah1[2], ah1[3], XH + aOff1 + ca);
        LDMX4(bq0[0], bq0[1], bq0[2], bq0[3], WB + bOff0 + cb);
        LDMX4(bq1[0], bq1[1], bq1[2], bq1[3], WB + bOff1 + cb);
        LDMX4(al0[0], al0[1], al0[2], al0[3], XL + aOff0 + ca);
        LDMX4(al1[0], al1[1], al1[2], al1[3], XL + aOff1 + ca);
        MMAF16(acc[0][0], ah0, bq0 + 0);
        MMAF16(acc[0][1], ah0, bq0 + 2);
        MMAF16(acc[0][2], ah0, bq1 + 0);
        MMAF16(acc[0][3], ah0, bq1 + 2);
        MMAF16(acc[1][0], ah1, bq0 + 0);
        MMAF16(acc[1][1], ah1, bq0 + 2);
        MMAF16(acc[1][2], ah1, bq1 + 0);
        MMAF16(acc[1][3], ah1, bq1 + 2);
        MMAF16(acc[0][0], al0, bq0 + 0);
        MMAF16(acc[0][1], al0, bq0 + 2);
        MMAF16(acc[0][2], al0, bq1 + 0);
        MMAF16(acc[0][3], al0, bq1 + 2);
        MMAF16(acc[1][0], al1, bq0 + 0);
        MMAF16(acc[1][1], al1, bq0 + 2);
        MMAF16(acc[1][2], al1, bq1 + 0);
        MMAF16(acc[1][3], al1, bq1 + 2);
    }
}

// ---------------------------------------------------------------------------
// Persistent fused kernel: attention + pooled + 3-layer MLP per 128-row tile.
// 148 CTAs x 512 threads (16 warps), ~42 tiles each.
// ---------------------------------------------------------------------------
__global__ void __launch_bounds__(512, 1) fused_kernel(
    const float* __restrict__ edges,
    const int* __restrict__ in_idx,
    const int* __restrict__ in_mask,
    const int* __restrict__ out_idx,
    const int* __restrict__ out_mask,
    const float* __restrict__ W0,
    const float* __restrict__ b0,
    const float* __restrict__ W1,
    const float* __restrict__ b1,
    const float* __restrict__ Wout,
    const float* __restrict__ bout,
    float* __restrict__ out)
{
    extern __shared__ char smem[];
    const uint32_t sb = smem_u32(smem);

    const int t    = threadIdx.x;
    const int lane = t & 31;
    const int w    = t >> 5;        // 0..15

    // ---- load W0/W1 -> single fp16 smem, ONCE ----
    {
        const int h = t & 127;
        const int q = t >> 7;       // 0..3, 4 chunks each
        const int key = h & 7;
        const float4* s0 = (const float4*)(W0 + (size_t)h * H_DIM + q * 32);
        const float4* s1 = (const float4*)(W1 + (size_t)h * H_DIM + q * 32);
#pragma unroll
        for (int c = 0; c < 4; ++c) {
            int chunk = q * 4 + c;
            uint32_t off = (uint32_t)h * 256u + (uint32_t)((chunk ^ key) << 4);
            {
                float4 f0 = s0[2 * c], f1 = s0[2 * c + 1];
                float f[8] = {f0.x, f0.y, f0.z, f0.w, f1.x, f1.y, f1.z, f1.w};
                *(uint4*)(smem + W0_B + off) = cvt8h(f);
            }
            {
                float4 f0 = s1[2 * c], f1 = s1[2 * c + 1];
                float f[8] = {f0.x, f0.y, f0.z, f0.w, f1.x, f1.y, f1.z, f1.w};
                *(uint4*)(smem + W1_B + off) = cvt8h(f);
            }
        }
    }

    // ---- per-lane GEMM geometry (warp tile 32m x 32n) ----
    const int m0  = (w & 3) * 32;
    const int n0  = (w >> 2) * 32;
    const int gid = lane >> 2;      // 0..7
    const int tig = lane & 3;       // 0..3
    const int sub = lane >> 3;      // 0..3
    const int r8  = lane & 7;
    const int aRow = m0 + (sub & 1) * 8 + r8;
    const uint32_t aOff0 = (uint32_t)aRow * 256u;
    const uint32_t aOff1 = (uint32_t)(aRow + 16) * 256u;
    const uint32_t aKey  = (uint32_t)r8;
    const uint32_t cbA   = (uint32_t)(sub >> 1);
    const int bRow = n0 + (sub >> 1) * 8 + r8;
    const uint32_t bOff0 = (uint32_t)bRow * 256u;
    const uint32_t bOff1 = (uint32_t)(bRow + 16) * 256u;
    const uint32_t bKey  = (uint32_t)r8;
    const uint32_t cbB   = (uint32_t)(sub & 1);

    const uint32_t XH = sb + XHI_B, XL = sb + XLO_B;

    float* PSf = (float*)(smem + PS_B);
    float* stage = (float*)(smem + STG_B);
    float* sEw = (float*)(smem + ATT_B + (size_t)w * 2176);

    // X-fill roles (independent of warp id)
    const int xrow = t & 127;
    const int xq   = t >> 7;        // 0..3

    for (int tile = blockIdx.x; tile < N_TILES; tile += gridDim.x) {
        const long base = (long)tile * 128;

        // ============ attention: 2 nodes per warp -> PS ============
#pragma unroll 1
        for (int ns = 0; ns < 2; ++ns) {
            const int node = tile * 32 + w * 2 + ns;

            int idx_l = 0, m_l = 0;
            if (lane < K_IN) {
                idx_l = in_idx[(size_t)node * K_IN + lane];
                m_l   = in_mask[(size_t)node * K_IN + lane];
            }

            float2 r[K_IN];
#pragma unroll
            for (int k = 0; k < K_IN; ++k) {
                int ek = __shfl_sync(0xffffffffu, idx_l, k);
                float2 v = *(const float2*)(edges + (size_t)ek * D_DIM + lane * 2);
                r[k] = v;
                *(float2*)(sEw + k * 68 + lane * 2) = v;
            }
            __syncwarp();

            const int q0 = lane >> 3;
            const int kk = lane & 7;
            const float4* Eq0 = (const float4*)(sEw + q0 * 68);
            const float4* Eq1 = (const float4*)(sEw + (q0 + 4) * 68);
            const float4* Ekp = (const float4*)(sEw + kk * 68);

            float s0 = 0.f, s1 = 0.f;
#pragma unroll
            for (int d4 = 0; d4 < 16; ++d4) {
                float4 b  = Ekp[d4];
                float4 a0 = Eq0[d4];
                float4 a1 = Eq1[d4];
                s0 += a0.x * b.x + a0.y * b.y + a0.z * b.z + a0.w * b.w;
                s1 += a1.x * b.x + a1.y * b.y + a1.z * b.z + a1.w * b.w;
            }
            s0 *= 0.125f;
            s1 *= 0.125f;

            int mk = __shfl_sync(0xffffffffu, m_l, kk);
            if (!mk) { s0 = -1e9f; s1 = -1e9f; }

            float mx0 = s0, mx1 = s1;
#pragma unroll
            for (int o = 1; o < 8; o <<= 1) {
                mx0 = fmaxf(mx0, __shfl_xor_sync(0xffffffffu, mx0, o));
                mx1 = fmaxf(mx1, __shfl_xor_sync(0xffffffffu, mx1, o));
            }
            float e0 = __expf(s0 - mx0);
            float e1 = __expf(s1 - mx1);
            float z0 = e0, z1 = e1;
#pragma unroll
            for (int o = 1; o < 8; o <<= 1) {
                z0 += __shfl_xor_sync(0xffffffffu, z0, o);
                z1 += __shfl_xor_sync(0xffffffffu, z1, o);
            }
            float a0 = e0 / z0;
            float a1 = e1 / z1;

            int mq0 = __shfl_sync(0xffffffffu, m_l, q0);
            int mq1 = __shfl_sync(0xffffffffu, m_l, q0 + 4);

            float v = (mq0 ? a0 : 0.f) + (mq1 ? a1 : 0.f);
            v += __shfl_xor_sync(0xffffffffu, v, 8);
            v += __shfl_xor_sync(0xffffffffu, v, 16);

            int cnt = m_l;
#pragma unroll
            for (int o = 1; o < 32; o <<= 1)
                cnt += __shfl_xor_sync(0xffffffffu, cnt, o);
            float inv_denom = 1.f / fmaxf((float)cnt, 1.f);

            float px = 0.f, py = 0.f;
#pragma unroll
            for (int k = 0; k < K_IN; ++k) {
                float wk = __shfl_sync(0xffffffffu, v, k);
                px += wk * r[k].x;
                py += wk * r[k].y;
            }
            *(float2*)(PSf + (size_t)(w * 2 + ns) * D_DIM + lane * 2) =
                make_float2(px * inv_denom, py * inv_denom);
        }

        // ---- edge-half X fill (independent of PS; overlaps attn latency) ----
        if (xq < 2) {
            long grow = base + xrow;
            int eidx = out_idx[grow];
            const float4* s4 = (const float4*)(edges + (size_t)eidx * D_DIM
                                               + xq * 32);
            const int cbase = xq * 4;
#pragma unroll
            for (int c = 0; c < 4; ++c) {
                float4 f0 = s4[2 * c], f1 = s4[2 * c + 1];
                float f[8] = {f0.x, f0.y, f0.z, f0.w, f1.x, f1.y, f1.z, f1.w};
                uint4 hv, lv;
                split8h(f, hv, lv);
                uint32_t off = swz(xrow, cbase + c);
                *(uint4*)(smem + XHI_B + off) = hv;
                *(uint4*)(smem + XLO_B + off) = lv;
            }
        }
        __syncthreads();   // PS ready (and W visible on first iter)

        // ---- pooled-half X fill ----
        if (xq >= 2) {
            const float* src = PSf + (size_t)(xrow >> 2) * D_DIM + (xq - 2) * 32;
            const float4* s4 = (const float4*)src;
            const int cbase = xq * 4;
#pragma unroll
            for (int c = 0; c < 4; ++c) {
                float4 f0 = s4[2 * c], f1 = s4[2 * c + 1];
                float f[8] = {f0.x, f0.y, f0.z, f0.w, f1.x, f1.y, f1.z, f1.w};
                uint4 hv, lv;
                split8h(f, hv, lv);
                uint32_t off = swz(xrow, cbase + c);
                *(uint4*)(smem + XHI_B + off) = hv;
                *(uint4*)(smem + XLO_B + off) = lv;
            }
        }
        __syncthreads();

        // ============ GEMM layer 1 ============
        float acc[2][4][4];
#pragma unroll
        for (int i = 0; i < 2; ++i)
#pragma unroll
            for (int j = 0; j < 4; ++j)
#pragma unroll
                for (int p = 0; p < 4; ++p) acc[i][j][p] = 0.f;

        gemm_fused(XH, XL, sb + W0_B,
                   aOff0, aOff1, aKey, cbA, bOff0, bOff1, bKey, cbB, acc);

        __syncthreads();   // all reads of X done before epilogue overwrites

        // ---- epilogue 1: H = relu(acc + b0) -> X buffers (fp16 hi/lo) ----
#pragma unroll
        for (int j = 0; j < 4; ++j) {
            int h0 = n0 + 8 * j + 2 * tig;
            float2 bb = *(const float2*)(b0 + h0);
            int chunk = (n0 + 8 * j) >> 3;
            uint32_t cof = (uint32_t)(tig * 4);
#pragma unroll
            for (int i = 0; i < 2; ++i) {
#pragma unroll
                for (int rs = 0; rs < 2; ++rs) {
                    int row = m0 + 16 * i + 8 * rs + gid;
                    float v0 = fmaxf(acc[i][j][2 * rs]     + bb.x, 0.f);
                    float v1 = fmaxf(acc[i][j][2 * rs + 1] + bb.y, 0.f);
                    __half h0h = __float2half_rn(v0);
                    __half h1h = __float2half_rn(v1);
                    float l0 = v0 - __half2float(h0h);
                    float l1 = v1 - __half2float(h1h);
                    uint32_t hw = f16x2_rn(__half2float(h0h), __half2float(h1h));
                    uint32_t lw = f16x2_rn(l0, l1);
                    uint32_t off = (uint32_t)row * 256u
                                 + (uint32_t)((chunk ^ (row & 7)) << 4) + cof;
                    *(uint32_t*)(smem + XHI_B + off) = hw;
                    *(uint32_t*)(smem + XLO_B + off) = lw;
                }
            }
        }
        __syncthreads();

        // ============ GEMM layer 2 ============
#pragma unroll
        for (int i = 0; i < 2; ++i)
#pragma unroll
            for (int j = 0; j < 4; ++j)
#pragma unroll
                for (int p = 0; p < 4; ++p) acc[i][j][p] = 0.f;

        gemm_fused(XH, XL, sb + W1_B,
                   aOff0, aOff1, aKey, cbA, bOff0, bOff1, bKey, cbB, acc);

        // ---- final epilogue: relu(+b1), dot Wout, reduce ----
        float y[2][2] = {{0.f, 0.f}, {0.f, 0.f}};
#pragma unroll
        for (int j = 0; j < 4; ++j) {
            int h0 = n0 + 8 * j + 2 * tig;
            float2 bb = *(const float2*)(b1 + h0);
            float2 ww = *(const float2*)(Wout + h0);
#pragma unroll
            for (int i = 0; i < 2; ++i) {
#pragma unroll
                for (int rs = 0; rs < 2; ++rs) {
                    float v0 = fmaxf(acc[i][j][2 * rs]     + bb.x, 0.f);
                    float v1 = fmaxf(acc[i][j][2 * rs + 1] + bb.y, 0.f);
                    y[i][rs] += ww.x * v0 + ww.y * v1;
                }
            }
        }
#pragma unroll
        for (int i = 0; i < 2; ++i)
#pragma unroll
            for (int rs = 0; rs < 2; ++rs) {
                y[i][rs] += __shfl_xor_sync(0xffffffffu, y[i][rs], 1);
                y[i][rs] += __shfl_xor_sync(0xffffffffu, y[i][rs], 2);
            }

        if (tig == 0) {
            int col = w >> 2;
#pragma unroll
            for (int i = 0; i < 2; ++i)
#pragma unroll
                for (int rs = 0; rs < 2; ++rs) {
                    int row = m0 + 16 * i + 8 * rs + gid;
                    stage[col * 128 + row] = y[i][rs];
                }
        }
        __syncthreads();   // stage ready; GEMM2 X-reads complete

        if (t < 128) {
            long row = base + t;
            float s = stage[t] + stage[128 + t] + stage[256 + t]
                    + stage[384 + t] + bout[0];
            out[row] = s * (float)out_mask[row];
        }
        __syncthreads();   // protect X/PS/stage before next tile's writes
    }
}

// ---------------------------------------------------------------------------
extern "C" void kernel_launch(void* const* d_in, const int* in_sizes, int n_in,
                              void* d_out, int out_size) {
    const float* edges   = (const float*)d_in[0];
    const int*   in_idx  = (const int*)d_in[1];
    const int*   in_mask = (const int*)d_in[2];
    const int*   out_idx = (const int*)d_in[3];
    const int*   out_mask= (const int*)d_in[4];
    const float* W0      = (const float*)d_in[5];
    const float* b0      = (const float*)d_in[6];
    const float* W1      = (const float*)d_in[7];
    const float* b1      = (const float*)d_in[8];
    const float* Wout    = (const float*)d_in[9];
    const float* bout    = (const float*)d_in[10];
    float* out = (float*)d_out;

    cudaFuncSetAttribute(fused_kernel,
                         cudaFuncAttributeMaxDynamicSharedMemorySize,
                         SMEM_TOTAL);
    fused_kernel<<<GRID_CTAS, 512, SMEM_TOTAL>>>(
        edges, in_idx, in_mask, out_idx, out_mask,
        W0, b0, W1, b1, Wout, bout, out);
}

// round 11
// speedup vs baseline: 1.7053x; 1.1421x over previous
#include <cuda_runtime.h>
#include <cuda_bf16.h>
#include <cuda_fp16.h>
#include <math.h>
#include <stdint.h>

// Problem constants: N=200000, K_IN=8, K_OUT=4, E=800000, D=64, H=128, O=1
#define D_DIM 64
#define K_IN 8
#define K_OUT 4
#define H_DIM 128
#define N_TILES 6250        // 800000 rows / 128 rows per tile
#define GRID_CTAS 148

// ---------------------------------------------------------------------------
// helpers
// ---------------------------------------------------------------------------
__device__ __forceinline__ uint32_t smem_u32(const void* p) {
    uint32_t a;
    asm("{ .reg .u64 t; cvta.to.shared.u64 t, %1; cvt.u32.u64 %0, t; }"
        : "=r"(a) : "l"(p));
    return a;
}

// pack two floats to f16x2: lo -> bits[15:0], hi -> bits[31:16]
__device__ __forceinline__ uint32_t f16x2_rn(float lo, float hi) {
    uint32_t r;
    asm("cvt.rn.f16x2.f32 %0, %1, %2;" : "=r"(r) : "f"(hi), "f"(lo));
    return r;
}

// split 8 fp32 into hi-fp16 16B chunk + lo-fp16 16B chunk
__device__ __forceinline__ void split8h(const float* f, uint4& hv, uint4& lv) {
    float hf[8], lf[8];
#pragma unroll
    for (int i = 0; i < 8; ++i) {
        __half hb = __float2half_rn(f[i]);
        hf[i] = __half2float(hb);
        lf[i] = f[i] - hf[i];
    }
    hv.x = f16x2_rn(hf[0], hf[1]); hv.y = f16x2_rn(hf[2], hf[3]);
    hv.z = f16x2_rn(hf[4], hf[5]); hv.w = f16x2_rn(hf[6], hf[7]);
    lv.x = f16x2_rn(lf[0], lf[1]); lv.y = f16x2_rn(lf[2], lf[3]);
    lv.z = f16x2_rn(lf[4], lf[5]); lv.w = f16x2_rn(lf[6], lf[7]);
}

// convert 8 fp32 to single fp16 16B chunk
__device__ __forceinline__ uint4 cvt8h(const float* f) {
    uint4 v;
    v.x = f16x2_rn(f[0], f[1]); v.y = f16x2_rn(f[2], f[3]);
    v.z = f16x2_rn(f[4], f[5]); v.w = f16x2_rn(f[6], f[7]);
    return v;
}

#define LDMX4(r0, r1, r2, r3, addr) \
    asm volatile("ldmatrix.sync.aligned.m8n8.x4.shared.b16 {%0,%1,%2,%3}, [%4];" \
        : "=r"(r0), "=r"(r1), "=r"(r2), "=r"(r3) : "r"(addr))

#define MMAF16(c, a, b) \
    asm volatile("mma.sync.aligned.m16n8k16.row.col.f32.f16.f16.f32 " \
        "{%0,%1,%2,%3}, {%4,%5,%6,%7}, {%8,%9}, {%0,%1,%2,%3};" \
        : "+f"((c)[0]), "+f"((c)[1]), "+f"((c)[2]), "+f"((c)[3]) \
        : "r"((a)[0]), "r"((a)[1]), "r"((a)[2]), "r"((a)[3]), \
          "r"((b)[0]), "r"((b)[1]))

// ---------------------------------------------------------------------------
// SMEM layout (bytes), one persistent CTA per SM:
//   XHI @ 0        [128 m][128 k] fp16 hi   (32 KB)  256B rows, XOR-16B swizzle
//   XLO @ 32768    (32 KB)
//   HB  @ 65536    [128 m][128 h] fp16 H (layer-1 output, single)  (32 KB)
//   W0  @ 98304    [128 h][128 k] fp16      (32 KB)
//   W1  @ 131072   (32 KB)
//   ATT @ 163840   16 warps x 2176 B attention staging (34816 B)
//   PS  @ 198656   32 nodes x 64 fp32 pooled scratch (8 KB)
//   STG @ 206848   4 x 128 fp32 partials (2 KB)
// Total 208896 bytes.
// ---------------------------------------------------------------------------
#define XHI_B   0u
#define XLO_B   32768u
#define HB_B    65536u
#define W0_B    98304u
#define W1_B    131072u
#define ATT_B   163840u
#define PS_B    198656u
#define STG_B   206848u
#define SMEM_TOTAL 208896

__device__ __forceinline__ uint32_t swz(int row, int chunk) {
    return (uint32_t)row * 256u + (uint32_t)((chunk ^ (row & 7)) << 4);
}

// 2-pass GEMM over k=128, warp tile 32m x 32n: acc += (Ahi + Alo) * W
__device__ __forceinline__ void gemm_2pass(
    uint32_t XH, uint32_t XL, uint32_t WB,
    uint32_t aOff0, uint32_t aOff1, uint32_t aKey, uint32_t cbA,
    uint32_t bOff0, uint32_t bOff1, uint32_t bKey, uint32_t cbB,
    float acc[2][4][4])
{
#pragma unroll
    for (int kc = 0; kc < 8; ++kc) {
        uint32_t ca = (uint32_t)((((uint32_t)(2 * kc) + cbA) ^ aKey) << 4);
        uint32_t cb = (uint32_t)((((uint32_t)(2 * kc) + cbB) ^ bKey) << 4);
        uint32_t ah0[4], ah1[4], al0[4], al1[4];
        uint32_t bq0[4], bq1[4];
        LDMX4(ah0[0], ah0[1], ah0[2], ah0[3], XH + aOff0 + ca);
        LDMX4(ah1[0], ah1[1], ah1[2], ah1[3], XH + aOff1 + ca);
        LDMX4(bq0[0], bq0[1], bq0[2], bq0[3], WB + bOff0 + cb);
        LDMX4(bq1[0], bq1[1], bq1[2], bq1[3], WB + bOff1 + cb);
        LDMX4(al0[0], al0[1], al0[2], al0[3], XL + aOff0 + ca);
        LDMX4(al1[0], al1[1], al1[2], al1[3], XL + aOff1 + ca);
        MMAF16(acc[0][0], ah0, bq0 + 0);
        MMAF16(acc[0][1], ah0, bq0 + 2);
        MMAF16(acc[0][2], ah0, bq1 + 0);
        MMAF16(acc[0][3], ah0, bq1 + 2);
        MMAF16(acc[1][0], ah1, bq0 + 0);
        MMAF16(acc[1][1], ah1, bq0 + 2);
        MMAF16(acc[1][2], ah1, bq1 + 0);
        MMAF16(acc[1][3], ah1, bq1 + 2);
        MMAF16(acc[0][0], al0, bq0 + 0);
        MMAF16(acc[0][1], al0, bq0 + 2);
        MMAF16(acc[0][2], al0, bq1 + 0);
        MMAF16(acc[0][3], al0, bq1 + 2);
        MMAF16(acc[1][0], al1, bq0 + 0);
        MMAF16(acc[1][1], al1, bq0 + 2);
        MMAF16(acc[1][2], al1, bq1 + 0);
        MMAF16(acc[1][3], al1, bq1 + 2);
    }
}

// 1-pass GEMM over k=128 (A single fp16): acc += A * W
__device__ __forceinline__ void gemm_1pass(
    uint32_t AB, uint32_t WB,
    uint32_t aOff0, uint32_t aOff1, uint32_t aKey, uint32_t cbA,
    uint32_t bOff0, uint32_t bOff1, uint32_t bKey, uint32_t cbB,
    float acc[2][4][4])
{
#pragma unroll
    for (int kc = 0; kc < 8; ++kc) {
        uint32_t ca = (uint32_t)((((uint32_t)(2 * kc) + cbA) ^ aKey) << 4);
        uint32_t cb = (uint32_t)((((uint32_t)(2 * kc) + cbB) ^ bKey) << 4);
        uint32_t a0[4], a1[4], bq0[4], bq1[4];
        LDMX4(a0[0], a0[1], a0[2], a0[3], AB + aOff0 + ca);
        LDMX4(a1[0], a1[1], a1[2], a1[3], AB + aOff1 + ca);
        LDMX4(bq0[0], bq0[1], bq0[2], bq0[3], WB + bOff0 + cb);
        LDMX4(bq1[0], bq1[1], bq1[2], bq1[3], WB + bOff1 + cb);
        MMAF16(acc[0][0], a0, bq0 + 0);
        MMAF16(acc[0][1], a0, bq0 + 2);
        MMAF16(acc[0][2], a0, bq1 + 0);
        MMAF16(acc[0][3], a0, bq1 + 2);
        MMAF16(acc[1][0], a1, bq0 + 0);
        MMAF16(acc[1][1], a1, bq0 + 2);
        MMAF16(acc[1][2], a1, bq1 + 0);
        MMAF16(acc[1][3], a1, bq1 + 2);
    }
}

// attention compute for one node, given staged rows + register copy.
// Writes pooled vector to PSf[slot].
__device__ __forceinline__ void attn_compute(
    const float* sEw, const float2* r, int m_l, int lane, float* PSf, int slot)
{
    const int q0 = lane >> 3;
    const int kk = lane & 7;
    const float4* Eq0 = (const float4*)(sEw + q0 * 68);
    const float4* Eq1 = (const float4*)(sEw + (q0 + 4) * 68);
    const float4* Ekp = (const float4*)(sEw + kk * 68);

    float s0 = 0.f, s1 = 0.f;
#pragma unroll
    for (int d4 = 0; d4 < 16; ++d4) {
        float4 b  = Ekp[d4];
        float4 a0 = Eq0[d4];
        float4 a1 = Eq1[d4];
        s0 += a0.x * b.x + a0.y * b.y + a0.z * b.z + a0.w * b.w;
        s1 += a1.x * b.x + a1.y * b.y + a1.z * b.z + a1.w * b.w;
    }
    s0 *= 0.125f;
    s1 *= 0.125f;

    int mk = __shfl_sync(0xffffffffu, m_l, kk);
    if (!mk) { s0 = -1e9f; s1 = -1e9f; }

    float mx0 = s0, mx1 = s1;
#pragma unroll
    for (int o = 1; o < 8; o <<= 1) {
        mx0 = fmaxf(mx0, __shfl_xor_sync(0xffffffffu, mx0, o));
        mx1 = fmaxf(mx1, __shfl_xor_sync(0xffffffffu, mx1, o));
    }
    float e0 = __expf(s0 - mx0);
    float e1 = __expf(s1 - mx1);
    float z0 = e0, z1 = e1;
#pragma unroll
    for (int o = 1; o < 8; o <<= 1) {
        z0 += __shfl_xor_sync(0xffffffffu, z0, o);
        z1 += __shfl_xor_sync(0xffffffffu, z1, o);
    }
    float a0 = e0 / z0;
    float a1 = e1 / z1;

    int mq0 = __shfl_sync(0xffffffffu, m_l, q0);
    int mq1 = __shfl_sync(0xffffffffu, m_l, q0 + 4);

    float v = (mq0 ? a0 : 0.f) + (mq1 ? a1 : 0.f);
    v += __shfl_xor_sync(0xffffffffu, v, 8);
    v += __shfl_xor_sync(0xffffffffu, v, 16);

    int cnt = m_l;
#pragma unroll
    for (int o = 1; o < 32; o <<= 1)
        cnt += __shfl_xor_sync(0xffffffffu, cnt, o);
    float inv_denom = 1.f / fmaxf((float)cnt, 1.f);

    float px = 0.f, py = 0.f;
#pragma unroll
    for (int k = 0; k < K_IN; ++k) {
        float wk = __shfl_sync(0xffffffffu, v, k);
        px += wk * r[k].x;
        py += wk * r[k].y;
    }
    *(float2*)(PSf + (size_t)slot * D_DIM + lane * 2) =
        make_float2(px * inv_denom, py * inv_denom);
}

// ---------------------------------------------------------------------------
// Persistent fused kernel: attention + pooled + 3-layer MLP per 128-row tile.
// 148 CTAs x 512 threads (16 warps), ~42 tiles each.
// ---------------------------------------------------------------------------
__global__ void __launch_bounds__(512, 1) fused_kernel(
    const float* __restrict__ edges,
    const int* __restrict__ in_idx,
    const int* __restrict__ in_mask,
    const int* __restrict__ out_idx,
    const int* __restrict__ out_mask,
    const float* __restrict__ W0,
    const float* __restrict__ b0,
    const float* __restrict__ W1,
    const float* __restrict__ b1,
    const float* __restrict__ Wout,
    const float* __restrict__ bout,
    float* __restrict__ out)
{
    extern __shared__ char smem[];
    const uint32_t sb = smem_u32(smem);

    const int t    = threadIdx.x;
    const int lane = t & 31;
    const int w    = t >> 5;        // 0..15

    // ---- load W0/W1 -> single fp16 smem, ONCE ----
    {
        const int h = t & 127;
        const int q = t >> 7;       // 0..3, 4 chunks each
        const int key = h & 7;
        const float4* s0 = (const float4*)(W0 + (size_t)h * H_DIM + q * 32);
        const float4* s1 = (const float4*)(W1 + (size_t)h * H_DIM + q * 32);
#pragma unroll
        for (int c = 0; c < 4; ++c) {
            int chunk = q * 4 + c;
            uint32_t off = (uint32_t)h * 256u + (uint32_t)((chunk ^ key) << 4);
            {
                float4 f0 = s0[2 * c], f1 = s0[2 * c + 1];
                float f[8] = {f0.x, f0.y, f0.z, f0.w, f1.x, f1.y, f1.z, f1.w};
                *(uint4*)(smem + W0_B + off) = cvt8h(f);
            }
            {
                float4 f0 = s1[2 * c], f1 = s1[2 * c + 1];
                float f[8] = {f0.x, f0.y, f0.z, f0.w, f1.x, f1.y, f1.z, f1.w};
                *(uint4*)(smem + W1_B + off) = cvt8h(f);
            }
        }
    }

    // ---- per-lane GEMM geometry (warp tile 32m x 32n) ----
    const int m0  = (w & 3) * 32;
    const int n0  = (w >> 2) * 32;
    const int gid = lane >> 2;      // 0..7
    const int tig = lane & 3;       // 0..3
    const int sub = lane >> 3;      // 0..3
    const int r8  = lane & 7;
    const int aRow = m0 + (sub & 1) * 8 + r8;
    const uint32_t aOff0 = (uint32_t)aRow * 256u;
    const uint32_t aOff1 = (uint32_t)(aRow + 16) * 256u;
    const uint32_t aKey  = (uint32_t)r8;
    const uint32_t cbA   = (uint32_t)(sub >> 1);
    const int bRow = n0 + (sub >> 1) * 8 + r8;
    const uint32_t bOff0 = (uint32_t)bRow * 256u;
    const uint32_t bOff1 = (uint32_t)(bRow + 16) * 256u;
    const uint32_t bKey  = (uint32_t)r8;
    const uint32_t cbB   = (uint32_t)(sub & 1);

    float* PSf = (float*)(smem + PS_B);
    float* stage = (float*)(smem + STG_B);
    float* sEw = (float*)(smem + ATT_B + (size_t)w * 2176);

    // X-fill roles
    const int xrow = t & 127;
    const int xq   = t >> 7;        // 0..3

    for (int tile = blockIdx.x; tile < N_TILES; tile += gridDim.x) {
        const long base = (long)tile * 128;

        // ============ attention: 2 nodes per warp, prefetched ============
        {
            const int nodeA = tile * 32 + w * 2;
            const int nodeB = nodeA + 1;

            int idxA = 0, mA = 0, idxB = 0, mB = 0;
            if (lane < K_IN) {
                idxA = in_idx[(size_t)nodeA * K_IN + lane];
                mA   = in_mask[(size_t)nodeA * K_IN + lane];
                idxB = in_idx[(size_t)nodeB * K_IN + lane];
                mB   = in_mask[(size_t)nodeB * K_IN + lane];
            }

            float2 rA[K_IN], rB[K_IN];
            // node A gathers -> regs + staging
#pragma unroll
            for (int k = 0; k < K_IN; ++k) {
                int ek = __shfl_sync(0xffffffffu, idxA, k);
                float2 v = *(const float2*)(edges + (size_t)ek * D_DIM + lane * 2);
                rA[k] = v;
                *(float2*)(sEw + k * 68 + lane * 2) = v;
            }
            // node B gathers -> regs only (issued early; latency hides under A)
#pragma unroll
            for (int k = 0; k < K_IN; ++k) {
                int ek = __shfl_sync(0xffffffffu, idxB, k);
                rB[k] = *(const float2*)(edges + (size_t)ek * D_DIM + lane * 2);
            }
            __syncwarp();
            attn_compute(sEw, rA, mA, lane, PSf, w * 2);
            __syncwarp();   // staging reads for A done
#pragma unroll
            for (int k = 0; k < K_IN; ++k)
                *(float2*)(sEw + k * 68 + lane * 2) = rB[k];
            __syncwarp();
            attn_compute(sEw, rB, mB, lane, PSf, w * 2 + 1);
        }

        // ---- edge-half X fill (independent of PS; overlaps attn latency) ----
        if (xq < 2) {
            long grow = base + xrow;
            int eidx = out_idx[grow];
            const float4* s4 = (const float4*)(edges + (size_t)eidx * D_DIM
                                               + xq * 32);
            const int cbase = xq * 4;
#pragma unroll
            for (int c = 0; c < 4; ++c) {
                float4 f0 = s4[2 * c], f1 = s4[2 * c + 1];
                float f[8] = {f0.x, f0.y, f0.z, f0.w, f1.x, f1.y, f1.z, f1.w};
                uint4 hv, lv;
                split8h(f, hv, lv);
                uint32_t off = swz(xrow, cbase + c);
                *(uint4*)(smem + XHI_B + off) = hv;
                *(uint4*)(smem + XLO_B + off) = lv;
            }
        }
        __syncthreads();   // barrier 1: PS ready (and W visible on iter 0)

        // ---- pooled-half X fill ----
        if (xq >= 2) {
            const float* src = PSf + (size_t)(xrow >> 2) * D_DIM + (xq - 2) * 32;
            const float4* s4 = (const float4*)src;
            const int cbase = xq * 4;
#pragma unroll
            for (int c = 0; c < 4; ++c) {
                float4 f0 = s4[2 * c], f1 = s4[2 * c + 1];
                float f[8] = {f0.x, f0.y, f0.z, f0.w, f1.x, f1.y, f1.z, f1.w};
                uint4 hv, lv;
                split8h(f, hv, lv);
                uint32_t off = swz(xrow, cbase + c);
                *(uint4*)(smem + XHI_B + off) = hv;
                *(uint4*)(smem + XLO_B + off) = lv;
            }
        }
        __syncthreads();   // barrier 2: X ready

        // ============ GEMM layer 1 (2-pass) ============
        float acc[2][4][4];
#pragma unroll
        for (int i = 0; i < 2; ++i)
#pragma unroll
            for (int j = 0; j < 4; ++j)
#pragma unroll
                for (int p = 0; p < 4; ++p) acc[i][j][p] = 0.f;

        gemm_2pass(sb + XHI_B, sb + XLO_B, sb + W0_B,
                   aOff0, aOff1, aKey, cbA, bOff0, bOff1, bKey, cbB, acc);

        // ---- epilogue 1: H = relu(acc + b0) -> HB (single fp16), no barrier
        //      needed before writes: HB reads of previous tile finished at
        //      the end-of-tile barrier.
#pragma unroll
        for (int j = 0; j < 4; ++j) {
            int h0 = n0 + 8 * j + 2 * tig;
            float2 bb = *(const float2*)(b0 + h0);
            int chunk = (n0 + 8 * j) >> 3;
            uint32_t cof = (uint32_t)(tig * 4);
#pragma unroll
            for (int i = 0; i < 2; ++i) {
#pragma unroll
                for (int rs = 0; rs < 2; ++rs) {
                    int row = m0 + 16 * i + 8 * rs + gid;
                    float v0 = fmaxf(acc[i][j][2 * rs]     + bb.x, 0.f);
                    float v1 = fmaxf(acc[i][j][2 * rs + 1] + bb.y, 0.f);
                    uint32_t hw = f16x2_rn(v0, v1);
                    uint32_t off = (uint32_t)row * 256u
                                 + (uint32_t)((chunk ^ (row & 7)) << 4) + cof;
                    *(uint32_t*)(smem + HB_B + off) = hw;
                }
            }
        }
        __syncthreads();   // barrier 3: HB ready

        // ============ GEMM layer 2 (1-pass, A = HB) ============
#pragma unroll
        for (int i = 0; i < 2; ++i)
#pragma unroll
            for (int j = 0; j < 4; ++j)
#pragma unroll
                for (int p = 0; p < 4; ++p) acc[i][j][p] = 0.f;

        gemm_1pass(sb + HB_B, sb + W1_B,
                   aOff0, aOff1, aKey, cbA, bOff0, bOff1, bKey, cbB, acc);

        // ---- final epilogue: relu(+b1), dot Wout, reduce ----
        float y[2][2] = {{0.f, 0.f}, {0.f, 0.f}};
#pragma unroll
        for (int j = 0; j < 4; ++j) {
            int h0 = n0 + 8 * j + 2 * tig;
            float2 bb = *(const float2*)(b1 + h0);
            float2 ww = *(const float2*)(Wout + h0);
#pragma unroll
            for (int i = 0; i < 2; ++i) {
#pragma unroll
                for (int rs = 0; rs < 2; ++rs) {
                    float v0 = fmaxf(acc[i][j][2 * rs]     + bb.x, 0.f);
                    float v1 = fmaxf(acc[i][j][2 * rs + 1] + bb.y, 0.f);
                    y[i][rs] += ww.x * v0 + ww.y * v1;
                }
            }
        }
#pragma unroll
        for (int i = 0; i < 2; ++i)
#pragma unroll
            for (int rs = 0; rs < 2; ++rs) {
                y[i][rs] += __shfl_xor_sync(0xffffffffu, y[i][rs], 1);
                y[i][rs] += __shfl_xor_sync(0xffffffffu, y[i][rs], 2);
            }

        if (tig == 0) {
            int col = w >> 2;
#pragma unroll
            for (int i = 0; i < 2; ++i)
#pragma unroll
                for (int rs = 0; rs < 2; ++rs) {
                    int row = m0 + 16 * i + 8 * rs + gid;
                    stage[col * 128 + row] = y[i][rs];
                }
        }
        __syncthreads();   // barrier 4: stage ready

        if (t < 128) {
            long row = base + t;
            float s = stage[t] + stage[128 + t] + stage[256 + t]
                    + stage[384 + t] + bout[0];
            out[row] = s * (float)out_mask[row];
        }
        __syncthreads();   // barrier 5: protect X/PS/HB/stage for next tile
    }
}

// ---------------------------------------------------------------------------
extern "C" void kernel_launch(void* const* d_in, const int* in_sizes, int n_in,
                              void* d_out, int out_size) {
    const float* edges   = (const float*)d_in[0];
    const int*   in_idx  = (const int*)d_in[1];
    const int*   in_mask = (const int*)d_in[2];
    const int*   out_idx = (const int*)d_in[3];
    const int*   out_mask= (const int*)d_in[4];
    const float* W0      = (const float*)d_in[5];
    const float* b0      = (const float*)d_in[6];
    const float* W1      = (const float*)d_in[7];
    const float* b1      = (const float*)d_in[8];
    const float* Wout    = (const float*)d_in[9];
    const float* bout    = (const float*)d_in[10];
    float* out = (float*)d_out;

    cudaFuncSetAttribute(fused_kernel,
                         cudaFuncAttributeMaxDynamicSharedMemorySize,
                         SMEM_TOTAL);
    fused_kernel<<<GRID_CTAS, 512, SMEM_TOTAL>>>(
        edges, in_idx, in_mask, out_idx, out_mask,
        W0, b0, W1, b1, Wout, bout, out);
}

// round 12
// speedup vs baseline: 1.9871x; 1.1652x over previous
#include <cuda_runtime.h>
#include <cuda_bf16.h>
#include <cuda_fp16.h>
#include <math.h>
#include <stdint.h>

// Problem constants: N=200000, K_IN=8, K_OUT=4, E=800000, D=64, H=128, O=1
#define D_DIM 64
#define K_IN 8
#define K_OUT 4
#define H_DIM 128
#define N_TILES 6250        // 800000 rows / 128 rows per tile
#define GRID_CTAS 148

// ---------------------------------------------------------------------------
// helpers
// ---------------------------------------------------------------------------
__device__ __forceinline__ uint32_t smem_u32(const void* p) {
    uint32_t a;
    asm("{ .reg .u64 t; cvta.to.shared.u64 t, %1; cvt.u32.u64 %0, t; }"
        : "=r"(a) : "l"(p));
    return a;
}

// pack two floats to f16x2: lo -> bits[15:0], hi -> bits[31:16]
__device__ __forceinline__ uint32_t f16x2_rn(float lo, float hi) {
    uint32_t r;
    asm("cvt.rn.f16x2.f32 %0, %1, %2;" : "=r"(r) : "f"(hi), "f"(lo));
    return r;
}

// split 8 fp32 into hi-fp16 16B chunk + lo-fp16 16B chunk
__device__ __forceinline__ void split8h(const float* f, uint4& hv, uint4& lv) {
    float hf[8], lf[8];
#pragma unroll
    for (int i = 0; i < 8; ++i) {
        __half hb = __float2half_rn(f[i]);
        hf[i] = __half2float(hb);
        lf[i] = f[i] - hf[i];
    }
    hv.x = f16x2_rn(hf[0], hf[1]); hv.y = f16x2_rn(hf[2], hf[3]);
    hv.z = f16x2_rn(hf[4], hf[5]); hv.w = f16x2_rn(hf[6], hf[7]);
    lv.x = f16x2_rn(lf[0], lf[1]); lv.y = f16x2_rn(lf[2], lf[3]);
    lv.z = f16x2_rn(lf[4], lf[5]); lv.w = f16x2_rn(lf[6], lf[7]);
}

// convert 8 fp32 to single fp16 16B chunk
__device__ __forceinline__ uint4 cvt8h(const float* f) {
    uint4 v;
    v.x = f16x2_rn(f[0], f[1]); v.y = f16x2_rn(f[2], f[3]);
    v.z = f16x2_rn(f[4], f[5]); v.w = f16x2_rn(f[6], f[7]);
    return v;
}

#define LDMX4(r0, r1, r2, r3, addr) \
    asm volatile("ldmatrix.sync.aligned.m8n8.x4.shared.b16 {%0,%1,%2,%3}, [%4];" \
        : "=r"(r0), "=r"(r1), "=r"(r2), "=r"(r3) : "r"(addr))

#define MMAF16(c, a, b) \
    asm volatile("mma.sync.aligned.m16n8k16.row.col.f32.f16.f16.f32 " \
        "{%0,%1,%2,%3}, {%4,%5,%6,%7}, {%8,%9}, {%0,%1,%2,%3};" \
        : "+f"((c)[0]), "+f"((c)[1]), "+f"((c)[2]), "+f"((c)[3]) \
        : "r"((a)[0]), "r"((a)[1]), "r"((a)[2]), "r"((a)[3]), \
          "r"((b)[0]), "r"((b)[1]))

// ---------------------------------------------------------------------------
// SMEM layout (bytes), one persistent CTA per SM:
//   XHI @ 0        [128 m][128 k] fp16 hi   (32 KB)  256B rows, XOR-16B swizzle
//   XLO @ 32768    (32 KB)
//   HB  @ 65536    [128 m][128 h] fp16 H    (32 KB)
//   W0  @ 98304    [128 h][128 k] fp16      (32 KB)
//   W1  @ 131072   (32 KB)
//   STG @ 163840   4 x 128 fp32 partials (2 KB)
// Total 165888 bytes.
// ---------------------------------------------------------------------------
#define XHI_B   0u
#define XLO_B   32768u
#define HB_B    65536u
#define W0_B    98304u
#define W1_B    131072u
#define STG_B   163840u
#define SMEM_TOTAL 165888

__device__ __forceinline__ uint32_t swz(int row, int chunk) {
    return (uint32_t)row * 256u + (uint32_t)((chunk ^ (row & 7)) << 4);
}

// 2-pass GEMM over k=128, warp tile 32m x 32n: acc += (Ahi + Alo) * W
__device__ __forceinline__ void gemm_2pass(
    uint32_t XH, uint32_t XL, uint32_t WB,
    uint32_t aOff0, uint32_t aOff1, uint32_t aKey, uint32_t cbA,
    uint32_t bOff0, uint32_t bOff1, uint32_t bKey, uint32_t cbB,
    float acc[2][4][4])
{
#pragma unroll
    for (int kc = 0; kc < 8; ++kc) {
        uint32_t ca = (uint32_t)((((uint32_t)(2 * kc) + cbA) ^ aKey) << 4);
        uint32_t cb = (uint32_t)((((uint32_t)(2 * kc) + cbB) ^ bKey) << 4);
        uint32_t ah0[4], ah1[4], al0[4], al1[4];
        uint32_t bq0[4], bq1[4];
        LDMX4(ah0[0], ah0[1], ah0[2], ah0[3], XH + aOff0 + ca);
        LDMX4(ah1[0], ah1[1], ah1[2], ah1[3], XH + aOff1 + ca);
        LDMX4(bq0[0], bq0[1], bq0[2], bq0[3], WB + bOff0 + cb);
        LDMX4(bq1[0], bq1[1], bq1[2], bq1[3], WB + bOff1 + cb);
        LDMX4(al0[0], al0[1], al0[2], al0[3], XL + aOff0 + ca);
        LDMX4(al1[0], al1[1], al1[2], al1[3], XL + aOff1 + ca);
        MMAF16(acc[0][0], ah0, bq0 + 0);
        MMAF16(acc[0][1], ah0, bq0 + 2);
        MMAF16(acc[0][2], ah0, bq1 + 0);
        MMAF16(acc[0][3], ah0, bq1 + 2);
        MMAF16(acc[1][0], ah1, bq0 + 0);
        MMAF16(acc[1][1], ah1, bq0 + 2);
        MMAF16(acc[1][2], ah1, bq1 + 0);
        MMAF16(acc[1][3], ah1, bq1 + 2);
        MMAF16(acc[0][0], al0, bq0 + 0);
        MMAF16(acc[0][1], al0, bq0 + 2);
        MMAF16(acc[0][2], al0, bq1 + 0);
        MMAF16(acc[0][3], al0, bq1 + 2);
        MMAF16(acc[1][0], al1, bq0 + 0);
        MMAF16(acc[1][1], al1, bq0 + 2);
        MMAF16(acc[1][2], al1, bq1 + 0);
        MMAF16(acc[1][3], al1, bq1 + 2);
    }
}

// 1-pass GEMM over k=128 (A single fp16): acc += A * W
__device__ __forceinline__ void gemm_1pass(
    uint32_t AB, uint32_t WB,
    uint32_t aOff0, uint32_t aOff1, uint32_t aKey, uint32_t cbA,
    uint32_t bOff0, uint32_t bOff1, uint32_t bKey, uint32_t cbB,
    float acc[2][4][4])
{
#pragma unroll
    for (int kc = 0; kc < 8; ++kc) {
        uint32_t ca = (uint32_t)((((uint32_t)(2 * kc) + cbA) ^ aKey) << 4);
        uint32_t cb = (uint32_t)((((uint32_t)(2 * kc) + cbB) ^ bKey) << 4);
        uint32_t a0[4], a1[4], bq0[4], bq1[4];
        LDMX4(a0[0], a0[1], a0[2], a0[3], AB + aOff0 + ca);
        LDMX4(a1[0], a1[1], a1[2], a1[3], AB + aOff1 + ca);
        LDMX4(bq0[0], bq0[1], bq0[2], bq0[3], WB + bOff0 + cb);
        LDMX4(bq1[0], bq1[1], bq1[2], bq1[3], WB + bOff1 + cb);
        MMAF16(acc[0][0], a0, bq0 + 0);
        MMAF16(acc[0][1], a0, bq0 + 2);
        MMAF16(acc[0][2], a0, bq1 + 0);
        MMAF16(acc[0][3], a0, bq1 + 2);
        MMAF16(acc[1][0], a1, bq0 + 0);
        MMAF16(acc[1][1], a1, bq0 + 2);
        MMAF16(acc[1][2], a1, bq1 + 0);
        MMAF16(acc[1][3], a1, bq1 + 2);
    }
}

// ---------------------------------------------------------------------------
// Register-only attention for one node. Lane ln holds r[k] = E[k][2ln:2ln+2].
// Gram partials from registers, recursive-halving butterfly (62 shfl), then
// softmax/mask/pool; pooled written directly into X pooled-half (fp16 hi/lo)
// at rows 4*nlocal..4*nlocal+3, cols 64..127. ZERO shared-memory reads.
// Mapping after reduction: lane ln holds scores p = 2*ln + i (i=0,1),
// i.e. q = ln>>2, k = 2*(ln&3)+i.
// ---------------------------------------------------------------------------
__device__ __forceinline__ void attn_node(
    const float2* r, int m_l, int ln, char* smem, int nlocal)
{
    const unsigned FULL = 0xffffffffu;
    const int sel1 = (ln >> 4) & 1;
    const int sel2 = (ln >> 3) & 1;
    const int sel3 = (ln >> 2) & 1;
    const int sel4 = (ln >> 1) & 1;
    const int sel5 = ln & 1;

    float h1[32];
#pragma unroll
    for (int i = 0; i < 32; ++i) {
        const int qa = i >> 3, ka = i & 7;
        float da = r[qa].x * r[ka].x + r[qa].y * r[ka].y;
        float db = r[qa + 4].x * r[ka].x + r[qa + 4].y * r[ka].y;
        float mine  = sel1 ? db : da;
        float their = sel1 ? da : db;
        h1[i] = mine + __shfl_xor_sync(FULL, their, 16);
    }
    float h2[16];
#pragma unroll
    for (int i = 0; i < 16; ++i) {
        float mine  = sel2 ? h1[i + 16] : h1[i];
        float their = sel2 ? h1[i] : h1[i + 16];
        h2[i] = mine + __shfl_xor_sync(FULL, their, 8);
    }
    float h3[8];
#pragma unroll
    for (int i = 0; i < 8; ++i) {
        float mine  = sel3 ? h2[i + 8] : h2[i];
        float their = sel3 ? h2[i] : h2[i + 8];
        h3[i] = mine + __shfl_xor_sync(FULL, their, 4);
    }
    float h4[4];
#pragma unroll
    for (int i = 0; i < 4; ++i) {
        float mine  = sel4 ? h3[i + 4] : h3[i];
        float their = sel4 ? h3[i] : h3[i + 4];
        h4[i] = mine + __shfl_xor_sync(FULL, their, 2);
    }
    float s0, s1;
    {
        float mine0  = sel5 ? h4[2] : h4[0];
        float their0 = sel5 ? h4[0] : h4[2];
        float mine1  = sel5 ? h4[3] : h4[1];
        float their1 = sel5 ? h4[1] : h4[3];
        s0 = (mine0 + __shfl_xor_sync(FULL, their0, 1)) * 0.125f;
        s1 = (mine1 + __shfl_xor_sync(FULL, their1, 1)) * 0.125f;
    }

    const int k0 = 2 * (ln & 3);
    int mk0 = __shfl_sync(FULL, m_l, k0);
    int mk1 = __shfl_sync(FULL, m_l, k0 + 1);
    if (!mk0) s0 = -1e9f;
    if (!mk1) s1 = -1e9f;

    // softmax over the 8 k's of this q (4 lanes x 2 values, xor 1,2)
    float mx = fmaxf(s0, s1);
    mx = fmaxf(mx, __shfl_xor_sync(FULL, mx, 1));
    mx = fmaxf(mx, __shfl_xor_sync(FULL, mx, 2));
    float e0 = __expf(s0 - mx), e1 = __expf(s1 - mx);
    float z = e0 + e1;
    z += __shfl_xor_sync(FULL, z, 1);
    z += __shfl_xor_sync(FULL, z, 2);
    float a0 = e0 / z, a1 = e1 / z;

    // w[k] = sum over valid queries (xor 4,8,16 sums over q)
    int mq = __shfl_sync(FULL, m_l, ln >> 2);
    float v0 = mq ? a0 : 0.f, v1 = mq ? a1 : 0.f;
#pragma unroll
    for (int o = 4; o < 32; o <<= 1) {
        v0 += __shfl_xor_sync(FULL, v0, o);
        v1 += __shfl_xor_sync(FULL, v1, o);
    }
    int cnt = __popc(__ballot_sync(FULL, m_l != 0));
    float inv_denom = 1.f / fmaxf((float)cnt, 1.f);

    float px = 0.f, py = 0.f;
#pragma unroll
    for (int k = 0; k < 8; ++k) {
        float wk = (k & 1) ? __shfl_sync(FULL, v1, k >> 1)
                           : __shfl_sync(FULL, v0, k >> 1);
        px += wk * r[k].x;
        py += wk * r[k].y;
    }
    px *= inv_denom;
    py *= inv_denom;

    // direct write to X pooled half (cols 64..127), rows 4*nlocal..+3
    __half ph = __float2half_rn(px);
    __half qh = __float2half_rn(py);
    float pl = px - __half2float(ph);
    float ql = py - __half2float(qh);
    uint32_t hw = f16x2_rn(__half2float(ph), __half2float(qh));
    uint32_t lw = f16x2_rn(pl, ql);
    const int chunk = 8 + (ln >> 2);
    const uint32_t cof = (uint32_t)((ln & 3) * 4);
#pragma unroll
    for (int rr = 0; rr < 4; ++rr) {
        int row = nlocal * 4 + rr;
        uint32_t off = (uint32_t)row * 256u
                     + (uint32_t)((chunk ^ (row & 7)) << 4) + cof;
        *(uint32_t*)(smem + XHI_B + off) = hw;
        *(uint32_t*)(smem + XLO_B + off) = lw;
    }
}

// ---------------------------------------------------------------------------
// Persistent fused kernel: attention + 3-layer MLP per 128-row tile.
// 148 CTAs x 512 threads (16 warps), ~42 tiles each.
// ---------------------------------------------------------------------------
__global__ void __launch_bounds__(512, 1) fused_kernel(
    const float* __restrict__ edges,
    const int* __restrict__ in_idx,
    const int* __restrict__ in_mask,
    const int* __restrict__ out_idx,
    const int* __restrict__ out_mask,
    const float* __restrict__ W0,
    const float* __restrict__ b0,
    const float* __restrict__ W1,
    const float* __restrict__ b1,
    const float* __restrict__ Wout,
    const float* __restrict__ bout,
    float* __restrict__ out)
{
    extern __shared__ char smem[];
    const uint32_t sb = smem_u32(smem);
    const unsigned FULL = 0xffffffffu;

    const int t    = threadIdx.x;
    const int lane = t & 31;
    const int w    = t >> 5;        // 0..15

    // ---- load W0/W1 -> single fp16 smem, ONCE ----
    {
        const int h = t & 127;
        const int q = t >> 7;       // 0..3, 4 chunks each
        const int key = h & 7;
        const float4* s0 = (const float4*)(W0 + (size_t)h * H_DIM + q * 32);
        const float4* s1 = (const float4*)(W1 + (size_t)h * H_DIM + q * 32);
#pragma unroll
        for (int c = 0; c < 4; ++c) {
            int chunk = q * 4 + c;
            uint32_t off = (uint32_t)h * 256u + (uint32_t)((chunk ^ key) << 4);
            {
                float4 f0 = s0[2 * c], f1 = s0[2 * c + 1];
                float f[8] = {f0.x, f0.y, f0.z, f0.w, f1.x, f1.y, f1.z, f1.w};
                *(uint4*)(smem + W0_B + off) = cvt8h(f);
            }
            {
                float4 f0 = s1[2 * c], f1 = s1[2 * c + 1];
                float f[8] = {f0.x, f0.y, f0.z, f0.w, f1.x, f1.y, f1.z, f1.w};
                *(uint4*)(smem + W1_B + off) = cvt8h(f);
            }
        }
    }

    // ---- per-lane GEMM geometry (warp tile 32m x 32n) ----
    const int m0  = (w & 3) * 32;
    const int n0  = (w >> 2) * 32;
    const int gid = lane >> 2;      // 0..7
    const int tig = lane & 3;       // 0..3
    const int sub = lane >> 3;      // 0..3
    const int r8  = lane & 7;
    const int aRow = m0 + (sub & 1) * 8 + r8;
    const uint32_t aOff0 = (uint32_t)aRow * 256u;
    const uint32_t aOff1 = (uint32_t)(aRow + 16) * 256u;
    const uint32_t aKey  = (uint32_t)r8;
    const uint32_t cbA   = (uint32_t)(sub >> 1);
    const int bRow = n0 + (sub >> 1) * 8 + r8;
    const uint32_t bOff0 = (uint32_t)bRow * 256u;
    const uint32_t bOff1 = (uint32_t)(bRow + 16) * 256u;
    const uint32_t bKey  = (uint32_t)r8;
    const uint32_t cbB   = (uint32_t)(sub & 1);

    float* stage = (float*)(smem + STG_B);

    // X-fill roles: 4 threads per row, 2 chunks (16 k) each
    const int xrow = t & 127;
    const int xq   = t >> 7;        // 0..3

    for (int tile = blockIdx.x; tile < N_TILES; tile += gridDim.x) {
        const long base = (long)tile * 128;

        // ============ attention: 2 nodes per warp, register-only ============
        {
            const int nodeA = tile * 32 + w * 2;
            const int nodeB = nodeA + 1;

            int idxA = 0, mA = 0, idxB = 0, mB = 0;
            if (lane < K_IN) {
                idxA = in_idx[(size_t)nodeA * K_IN + lane];
                mA   = in_mask[(size_t)nodeA * K_IN + lane];
                idxB = in_idx[(size_t)nodeB * K_IN + lane];
                mB   = in_mask[(size_t)nodeB * K_IN + lane];
            }

            float2 rA[K_IN], rB[K_IN];
#pragma unroll
            for (int k = 0; k < K_IN; ++k) {
                int ek = __shfl_sync(FULL, idxA, k);
                rA[k] = *(const float2*)(edges + (size_t)ek * D_DIM + lane * 2);
            }
#pragma unroll
            for (int k = 0; k < K_IN; ++k) {
                int ek = __shfl_sync(FULL, idxB, k);
                rB[k] = *(const float2*)(edges + (size_t)ek * D_DIM + lane * 2);
            }
            attn_node(rA, mA, lane, smem, w * 2);
            attn_node(rB, mB, lane, smem, w * 2 + 1);
        }

        // ---- edge-half X fill: all 512 threads, 2 chunks each ----
        {
            long grow = base + xrow;
            int eidx = out_idx[grow];
            const float4* s4 = (const float4*)(edges + (size_t)eidx * D_DIM
                                               + xq * 16);
#pragma unroll
            for (int c = 0; c < 2; ++c) {
                float4 f0 = s4[2 * c], f1 = s4[2 * c + 1];
                float f[8] = {f0.x, f0.y, f0.z, f0.w, f1.x, f1.y, f1.z, f1.w};
                uint4 hv, lv;
                split8h(f, hv, lv);
                uint32_t off = swz(xrow, 2 * xq + c);
                *(uint4*)(smem + XHI_B + off) = hv;
                *(uint4*)(smem + XLO_B + off) = lv;
            }
        }
        __syncthreads();   // barrier A: X fully ready (W visible on iter 0)

        // ============ GEMM layer 1 (2-pass) ============
        float acc[2][4][4];
#pragma unroll
        for (int i = 0; i < 2; ++i)
#pragma unroll
            for (int j = 0; j < 4; ++j)
#pragma unroll
                for (int p = 0; p < 4; ++p) acc[i][j][p] = 0.f;

        gemm_2pass(sb + XHI_B, sb + XLO_B, sb + W0_B,
                   aOff0, aOff1, aKey, cbA, bOff0, bOff1, bKey, cbB, acc);

        // ---- epilogue 1: H = relu(acc + b0) -> HB (single fp16) ----
#pragma unroll
        for (int j = 0; j < 4; ++j) {
            int h0 = n0 + 8 * j + 2 * tig;
            float2 bb = *(const float2*)(b0 + h0);
            int chunk = (n0 + 8 * j) >> 3;
            uint32_t cof = (uint32_t)(tig * 4);
#pragma unroll
            for (int i = 0; i < 2; ++i) {
#pragma unroll
                for (int rs = 0; rs < 2; ++rs) {
                    int row = m0 + 16 * i + 8 * rs + gid;
                    float v0 = fmaxf(acc[i][j][2 * rs]     + bb.x, 0.f);
                    float v1 = fmaxf(acc[i][j][2 * rs + 1] + bb.y, 0.f);
                    uint32_t hw = f16x2_rn(v0, v1);
                    uint32_t off = (uint32_t)row * 256u
                                 + (uint32_t)((chunk ^ (row & 7)) << 4) + cof;
                    *(uint32_t*)(smem + HB_B + off) = hw;
                }
            }
        }
        __syncthreads();   // barrier B: HB ready

        // ============ GEMM layer 2 (1-pass, A = HB) ============
#pragma unroll
        for (int i = 0; i < 2; ++i)
#pragma unroll
            for (int j = 0; j < 4; ++j)
#pragma unroll
                for (int p = 0; p < 4; ++p) acc[i][j][p] = 0.f;

        gemm_1pass(sb + HB_B, sb + W1_B,
                   aOff0, aOff1, aKey, cbA, bOff0, bOff1, bKey, cbB, acc);

        // ---- final epilogue: relu(+b1), dot Wout, reduce ----
        float y[2][2] = {{0.f, 0.f}, {0.f, 0.f}};
#pragma unroll
        for (int j = 0; j < 4; ++j) {
            int h0 = n0 + 8 * j + 2 * tig;
            float2 bb = *(const float2*)(b1 + h0);
            float2 ww = *(const float2*)(Wout + h0);
#pragma unroll
            for (int i = 0; i < 2; ++i) {
#pragma unroll
                for (int rs = 0; rs < 2; ++rs) {
                    float v0 = fmaxf(acc[i][j][2 * rs]     + bb.x, 0.f);
                    float v1 = fmaxf(acc[i][j][2 * rs + 1] + bb.y, 0.f);
                    y[i][rs] += ww.x * v0 + ww.y * v1;
                }
            }
        }
#pragma unroll
        for (int i = 0; i < 2; ++i)
#pragma unroll
            for (int rs = 0; rs < 2; ++rs) {
                y[i][rs] += __shfl_xor_sync(FULL, y[i][rs], 1);
                y[i][rs] += __shfl_xor_sync(FULL, y[i][rs], 2);
            }

        if (tig == 0) {
            int col = w >> 2;
#pragma unroll
            for (int i = 0; i < 2; ++i)
#pragma unroll
                for (int rs = 0; rs < 2; ++rs) {
                    int row = m0 + 16 * i + 8 * rs + gid;
                    stage[col * 128 + row] = y[i][rs];
                }
        }
        __syncthreads();   // barrier C: stage ready

        if (t < 128) {
            long row = base + t;
            float s = stage[t] + stage[128 + t] + stage[256 + t]
                    + stage[384 + t] + bout[0];
            out[row] = s * (float)out_mask[row];
        }
        __syncthreads();   // barrier D: protect X/HB/stage for next tile
    }
}

// ---------------------------------------------------------------------------
extern "C" void kernel_launch(void* const* d_in, const int* in_sizes, int n_in,
                              void* d_out, int out_size) {
    const float* edges   = (const float*)d_in[0];
    const int*   in_idx  = (const int*)d_in[1];
    const int*   in_mask = (const int*)d_in[2];
    const int*   out_idx = (const int*)d_in[3];
    const int*   out_mask= (const int*)d_in[4];
    const float* W0      = (const float*)d_in[5];
    const float* b0      = (const float*)d_in[6];
    const float* W1      = (const float*)d_in[7];
    const float* b1      = (const float*)d_in[8];
    const float* Wout    = (const float*)d_in[9];
    const float* bout    = (const float*)d_in[10];
    float* out = (float*)d_out;

    cudaFuncSetAttribute(fused_kernel,
                         cudaFuncAttributeMaxDynamicSharedMemorySize,
                         SMEM_TOTAL);
    fused_kernel<<<GRID_CTAS, 512, SMEM_TOTAL>>>(
        edges, in_idx, in_mask, out_idx, out_mask,
        W0, b0, W1, b1, Wout, bout, out);
}

// round 13
// speedup vs baseline: 2.2475x; 1.1311x over previous
#include <cuda_runtime.h>
#include <cuda_bf16.h>
#include <cuda_fp16.h>
#include <math.h>
#include <stdint.h>

// Problem constants: N=200000, K_IN=8, K_OUT=4, E=800000, D=64, H=128, O=1
#define D_DIM 64
#define K_IN 8
#define K_OUT 4
#define H_DIM 128
#define N_TILES 6250        // 800000 rows / 128 rows per tile
#define GRID_CTAS 148

// ---------------------------------------------------------------------------
// helpers
// ---------------------------------------------------------------------------
__device__ __forceinline__ uint32_t smem_u32(const void* p) {
    uint32_t a;
    asm("{ .reg .u64 t; cvta.to.shared.u64 t, %1; cvt.u32.u64 %0, t; }"
        : "=r"(a) : "l"(p));
    return a;
}

// pack two floats to f16x2: lo -> bits[15:0], hi -> bits[31:16]
__device__ __forceinline__ uint32_t f16x2_rn(float lo, float hi) {
    uint32_t r;
    asm("cvt.rn.f16x2.f32 %0, %1, %2;" : "=r"(r) : "f"(hi), "f"(lo));
    return r;
}

// convert 8 fp32 to single fp16 16B chunk
__device__ __forceinline__ uint4 cvt8h(const float* f) {
    uint4 v;
    v.x = f16x2_rn(f[0], f[1]); v.y = f16x2_rn(f[2], f[3]);
    v.z = f16x2_rn(f[4], f[5]); v.w = f16x2_rn(f[6], f[7]);
    return v;
}

#define LDMX4(r0, r1, r2, r3, addr) \
    asm volatile("ldmatrix.sync.aligned.m8n8.x4.shared.b16 {%0,%1,%2,%3}, [%4];" \
        : "=r"(r0), "=r"(r1), "=r"(r2), "=r"(r3) : "r"(addr))

#define MMAF16(c, a, b) \
    asm volatile("mma.sync.aligned.m16n8k16.row.col.f32.f16.f16.f32 " \
        "{%0,%1,%2,%3}, {%4,%5,%6,%7}, {%8,%9}, {%0,%1,%2,%3};" \
        : "+f"((c)[0]), "+f"((c)[1]), "+f"((c)[2]), "+f"((c)[3]) \
        : "r"((a)[0]), "r"((a)[1]), "r"((a)[2]), "r"((a)[3]), \
          "r"((b)[0]), "r"((b)[1]))

// ---------------------------------------------------------------------------
// SMEM layout (bytes), one persistent CTA per SM:
//   XB  @ 0        [128 m][128 k] fp16 X    (32 KB)  256B rows, XOR-16B swizzle
//   HB  @ 32768    [128 m][128 h] fp16 H    (32 KB)
//   W0  @ 65536    [128 h][128 k] fp16      (32 KB)
//   W1  @ 98304    (32 KB)
//   STG @ 131072   4 x 128 fp32 partials (2 KB)
// Total 133120 bytes.
// ---------------------------------------------------------------------------
#define XB_B    0u
#define HB_B    32768u
#define W0_B    65536u
#define W1_B    98304u
#define STG_B   131072u
#define SMEM_TOTAL 133120

__device__ __forceinline__ uint32_t swz(int row, int chunk) {
    return (uint32_t)row * 256u + (uint32_t)((chunk ^ (row & 7)) << 4);
}

// 1-pass GEMM over k=128 (A single fp16), warp tile 32m x 32n: acc += A * W
__device__ __forceinline__ void gemm_1pass(
    uint32_t AB, uint32_t WB,
    uint32_t aOff0, uint32_t aOff1, uint32_t aKey, uint32_t cbA,
    uint32_t bOff0, uint32_t bOff1, uint32_t bKey, uint32_t cbB,
    float acc[2][4][4])
{
#pragma unroll
    for (int kc = 0; kc < 8; ++kc) {
        uint32_t ca = (uint32_t)((((uint32_t)(2 * kc) + cbA) ^ aKey) << 4);
        uint32_t cb = (uint32_t)((((uint32_t)(2 * kc) + cbB) ^ bKey) << 4);
        uint32_t a0[4], a1[4], bq0[4], bq1[4];
        LDMX4(a0[0], a0[1], a0[2], a0[3], AB + aOff0 + ca);
        LDMX4(a1[0], a1[1], a1[2], a1[3], AB + aOff1 + ca);
        LDMX4(bq0[0], bq0[1], bq0[2], bq0[3], WB + bOff0 + cb);
        LDMX4(bq1[0], bq1[1], bq1[2], bq1[3], WB + bOff1 + cb);
        MMAF16(acc[0][0], a0, bq0 + 0);
        MMAF16(acc[0][1], a0, bq0 + 2);
        MMAF16(acc[0][2], a0, bq1 + 0);
        MMAF16(acc[0][3], a0, bq1 + 2);
        MMAF16(acc[1][0], a1, bq0 + 0);
        MMAF16(acc[1][1], a1, bq0 + 2);
        MMAF16(acc[1][2], a1, bq1 + 0);
        MMAF16(acc[1][3], a1, bq1 + 2);
    }
}

// ---------------------------------------------------------------------------
// Register-only attention for one node. Lane ln holds r[k] = E[k][2ln:2ln+2].
// Gram partials from registers, recursive-halving butterfly (62 shfl), then
// softmax/mask/pool; pooled written directly into X pooled-half (single fp16)
// at rows 4*nlocal..4*nlocal+3, cols 64..127. ZERO shared-memory reads.
// ---------------------------------------------------------------------------
__device__ __forceinline__ void attn_node(
    const float2* r, int m_l, int ln, char* smem, int nlocal)
{
    const unsigned FULL = 0xffffffffu;
    const int sel1 = (ln >> 4) & 1;
    const int sel2 = (ln >> 3) & 1;
    const int sel3 = (ln >> 2) & 1;
    const int sel4 = (ln >> 1) & 1;
    const int sel5 = ln & 1;

    float h1[32];
#pragma unroll
    for (int i = 0; i < 32; ++i) {
        const int qa = i >> 3, ka = i & 7;
        float da = r[qa].x * r[ka].x + r[qa].y * r[ka].y;
        float db = r[qa + 4].x * r[ka].x + r[qa + 4].y * r[ka].y;
        float mine  = sel1 ? db : da;
        float their = sel1 ? da : db;
        h1[i] = mine + __shfl_xor_sync(FULL, their, 16);
    }
    float h2[16];
#pragma unroll
    for (int i = 0; i < 16; ++i) {
        float mine  = sel2 ? h1[i + 16] : h1[i];
        float their = sel2 ? h1[i] : h1[i + 16];
        h2[i] = mine + __shfl_xor_sync(FULL, their, 8);
    }
    float h3[8];
#pragma unroll
    for (int i = 0; i < 8; ++i) {
        float mine  = sel3 ? h2[i + 8] : h2[i];
        float their = sel3 ? h2[i] : h2[i + 8];
        h3[i] = mine + __shfl_xor_sync(FULL, their, 4);
    }
    float h4[4];
#pragma unroll
    for (int i = 0; i < 4; ++i) {
        float mine  = sel4 ? h3[i + 4] : h3[i];
        float their = sel4 ? h3[i] : h3[i + 4];
        h4[i] = mine + __shfl_xor_sync(FULL, their, 2);
    }
    float s0, s1;
    {
        float mine0  = sel5 ? h4[2] : h4[0];
        float their0 = sel5 ? h4[0] : h4[2];
        float mine1  = sel5 ? h4[3] : h4[1];
        float their1 = sel5 ? h4[1] : h4[3];
        s0 = (mine0 + __shfl_xor_sync(FULL, their0, 1)) * 0.125f;
        s1 = (mine1 + __shfl_xor_sync(FULL, their1, 1)) * 0.125f;
    }

    const int k0 = 2 * (ln & 3);
    int mk0 = __shfl_sync(FULL, m_l, k0);
    int mk1 = __shfl_sync(FULL, m_l, k0 + 1);
    if (!mk0) s0 = -1e9f;
    if (!mk1) s1 = -1e9f;

    // softmax over the 8 k's of this q (4 lanes x 2 values, xor 1,2)
    float mx = fmaxf(s0, s1);
    mx = fmaxf(mx, __shfl_xor_sync(FULL, mx, 1));
    mx = fmaxf(mx, __shfl_xor_sync(FULL, mx, 2));
    float e0 = __expf(s0 - mx), e1 = __expf(s1 - mx);
    float z = e0 + e1;
    z += __shfl_xor_sync(FULL, z, 1);
    z += __shfl_xor_sync(FULL, z, 2);
    float a0 = e0 / z, a1 = e1 / z;

    // w[k] = sum over valid queries (xor 4,8,16 sums over q)
    int mq = __shfl_sync(FULL, m_l, ln >> 2);
    float v0 = mq ? a0 : 0.f, v1 = mq ? a1 : 0.f;
#pragma unroll
    for (int o = 4; o < 32; o <<= 1) {
        v0 += __shfl_xor_sync(FULL, v0, o);
        v1 += __shfl_xor_sync(FULL, v1, o);
    }
    int cnt = __popc(__ballot_sync(FULL, m_l != 0));
    float inv_denom = 1.f / fmaxf((float)cnt, 1.f);

    float px = 0.f, py = 0.f;
#pragma unroll
    for (int k = 0; k < 8; ++k) {
        float wk = (k & 1) ? __shfl_sync(FULL, v1, k >> 1)
                           : __shfl_sync(FULL, v0, k >> 1);
        px += wk * r[k].x;
        py += wk * r[k].y;
    }
    px *= inv_denom;
    py *= inv_denom;

    // direct write to X pooled half (cols 64..127), rows 4*nlocal..+3
    uint32_t hw = f16x2_rn(px, py);
    const int chunk = 8 + (ln >> 2);
    const uint32_t cof = (uint32_t)((ln & 3) * 4);
#pragma unroll
    for (int rr = 0; rr < 4; ++rr) {
        int row = nlocal * 4 + rr;
        uint32_t off = (uint32_t)row * 256u
                     + (uint32_t)((chunk ^ (row & 7)) << 4) + cof;
        *(uint32_t*)(smem + XB_B + off) = hw;
    }
}

// ---------------------------------------------------------------------------
// Persistent fused kernel: attention + 3-layer MLP per 128-row tile.
// 148 CTAs x 512 threads (16 warps), ~42 tiles each.
// ---------------------------------------------------------------------------
__global__ void __launch_bounds__(512, 1) fused_kernel(
    const float* __restrict__ edges,
    const int* __restrict__ in_idx,
    const int* __restrict__ in_mask,
    const int* __restrict__ out_idx,
    const int* __restrict__ out_mask,
    const float* __restrict__ W0,
    const float* __restrict__ b0,
    const float* __restrict__ W1,
    const float* __restrict__ b1,
    const float* __restrict__ Wout,
    const float* __restrict__ bout,
    float* __restrict__ out)
{
    extern __shared__ char smem[];
    const uint32_t sb = smem_u32(smem);
    const unsigned FULL = 0xffffffffu;

    const int t    = threadIdx.x;
    const int lane = t & 31;
    const int w    = t >> 5;        // 0..15

    // ---- load W0/W1 -> single fp16 smem, ONCE ----
    {
        const int h = t & 127;
        const int q = t >> 7;       // 0..3, 4 chunks each
        const int key = h & 7;
        const float4* s0 = (const float4*)(W0 + (size_t)h * H_DIM + q * 32);
        const float4* s1 = (const float4*)(W1 + (size_t)h * H_DIM + q * 32);
#pragma unroll
        for (int c = 0; c < 4; ++c) {
            int chunk = q * 4 + c;
            uint32_t off = (uint32_t)h * 256u + (uint32_t)((chunk ^ key) << 4);
            {
                float4 f0 = s0[2 * c], f1 = s0[2 * c + 1];
                float f[8] = {f0.x, f0.y, f0.z, f0.w, f1.x, f1.y, f1.z, f1.w};
                *(uint4*)(smem + W0_B + off) = cvt8h(f);
            }
            {
                float4 f0 = s1[2 * c], f1 = s1[2 * c + 1];
                float f[8] = {f0.x, f0.y, f0.z, f0.w, f1.x, f1.y, f1.z, f1.w};
                *(uint4*)(smem + W1_B + off) = cvt8h(f);
            }
        }
    }

    // ---- per-lane GEMM geometry (warp tile 32m x 32n) ----
    const int m0  = (w & 3) * 32;
    const int n0  = (w >> 2) * 32;
    const int gid = lane >> 2;      // 0..7
    const int tig = lane & 3;       // 0..3
    const int sub = lane >> 3;      // 0..3
    const int r8  = lane & 7;
    const int aRow = m0 + (sub & 1) * 8 + r8;
    const uint32_t aOff0 = (uint32_t)aRow * 256u;
    const uint32_t aOff1 = (uint32_t)(aRow + 16) * 256u;
    const uint32_t aKey  = (uint32_t)r8;
    const uint32_t cbA   = (uint32_t)(sub >> 1);
    const int bRow = n0 + (sub >> 1) * 8 + r8;
    const uint32_t bOff0 = (uint32_t)bRow * 256u;
    const uint32_t bOff1 = (uint32_t)(bRow + 16) * 256u;
    const uint32_t bKey  = (uint32_t)r8;
    const uint32_t cbB   = (uint32_t)(sub & 1);

    float* stage = (float*)(smem + STG_B);

    // X-fill roles: 4 threads per row, 2 chunks (16 k) each
    const int xrow = t & 127;
    const int xq   = t >> 7;        // 0..3

    for (int tile = blockIdx.x; tile < N_TILES; tile += gridDim.x) {
        const long base = (long)tile * 128;

        // ============ attention: 2 nodes per warp, register-only ============
        {
            const int nodeA = tile * 32 + w * 2;
            const int nodeB = nodeA + 1;

            int idxA = 0, mA = 0, idxB = 0, mB = 0;
            if (lane < K_IN) {
                idxA = in_idx[(size_t)nodeA * K_IN + lane];
                mA   = in_mask[(size_t)nodeA * K_IN + lane];
                idxB = in_idx[(size_t)nodeB * K_IN + lane];
                mB   = in_mask[(size_t)nodeB * K_IN + lane];
            }

            float2 rA[K_IN], rB[K_IN];
#pragma unroll
            for (int k = 0; k < K_IN; ++k) {
                int ek = __shfl_sync(FULL, idxA, k);
                rA[k] = *(const float2*)(edges + (size_t)ek * D_DIM + lane * 2);
            }
#pragma unroll
            for (int k = 0; k < K_IN; ++k) {
                int ek = __shfl_sync(FULL, idxB, k);
                rB[k] = *(const float2*)(edges + (size_t)ek * D_DIM + lane * 2);
            }
            attn_node(rA, mA, lane, smem, w * 2);
            attn_node(rB, mB, lane, smem, w * 2 + 1);
        }

        // ---- edge-half X fill: all 512 threads, 2 chunks each ----
        {
            long grow = base + xrow;
            int eidx = out_idx[grow];
            const float4* s4 = (const float4*)(edges + (size_t)eidx * D_DIM
                                               + xq * 16);
#pragma unroll
            for (int c = 0; c < 2; ++c) {
                float4 f0 = s4[2 * c], f1 = s4[2 * c + 1];
                float f[8] = {f0.x, f0.y, f0.z, f0.w, f1.x, f1.y, f1.z, f1.w};
                uint32_t off = swz(xrow, 2 * xq + c);
                *(uint4*)(smem + XB_B + off) = cvt8h(f);
            }
        }
        __syncthreads();   // barrier A: X fully ready (W visible on iter 0)

        // ============ GEMM layer 1 (1-pass, A = XB) ============
        float acc[2][4][4];
#pragma unroll
        for (int i = 0; i < 2; ++i)
#pragma unroll
            for (int j = 0; j < 4; ++j)
#pragma unroll
                for (int p = 0; p < 4; ++p) acc[i][j][p] = 0.f;

        gemm_1pass(sb + XB_B, sb + W0_B,
                   aOff0, aOff1, aKey, cbA, bOff0, bOff1, bKey, cbB, acc);

        // ---- epilogue 1: H = relu(acc + b0) -> HB (single fp16) ----
#pragma unroll
        for (int j = 0; j < 4; ++j) {
            int h0 = n0 + 8 * j + 2 * tig;
            float2 bb = *(const float2*)(b0 + h0);
            int chunk = (n0 + 8 * j) >> 3;
            uint32_t cof = (uint32_t)(tig * 4);
#pragma unroll
            for (int i = 0; i < 2; ++i) {
#pragma unroll
                for (int rs = 0; rs < 2; ++rs) {
                    int row = m0 + 16 * i + 8 * rs + gid;
                    float v0 = fmaxf(acc[i][j][2 * rs]     + bb.x, 0.f);
                    float v1 = fmaxf(acc[i][j][2 * rs + 1] + bb.y, 0.f);
                    uint32_t hw = f16x2_rn(v0, v1);
                    uint32_t off = (uint32_t)row * 256u
                                 + (uint32_t)((chunk ^ (row & 7)) << 4) + cof;
                    *(uint32_t*)(smem + HB_B + off) = hw;
                }
            }
        }
        __syncthreads();   // barrier B: HB ready

        // ============ GEMM layer 2 (1-pass, A = HB) ============
#pragma unroll
        for (int i = 0; i < 2; ++i)
#pragma unroll
            for (int j = 0; j < 4; ++j)
#pragma unroll
                for (int p = 0; p < 4; ++p) acc[i][j][p] = 0.f;

        gemm_1pass(sb + HB_B, sb + W1_B,
                   aOff0, aOff1, aKey, cbA, bOff0, bOff1, bKey, cbB, acc);

        // ---- final epilogue: relu(+b1), dot Wout, reduce ----
        float y[2][2] = {{0.f, 0.f}, {0.f, 0.f}};
#pragma unroll
        for (int j = 0; j < 4; ++j) {
            int h0 = n0 + 8 * j + 2 * tig;
            float2 bb = *(const float2*)(b1 + h0);
            float2 ww = *(const float2*)(Wout + h0);
#pragma unroll
            for (int i = 0; i < 2; ++i) {
#pragma unroll
                for (int rs = 0; rs < 2; ++rs) {
                    float v0 = fmaxf(acc[i][j][2 * rs]     + bb.x, 0.f);
                    float v1 = fmaxf(acc[i][j][2 * rs + 1] + bb.y, 0.f);
                    y[i][rs] += ww.x * v0 + ww.y * v1;
                }
            }
        }
#pragma unroll
        for (int i = 0; i < 2; ++i)
#pragma unroll
            for (int rs = 0; rs < 2; ++rs) {
                y[i][rs] += __shfl_xor_sync(FULL, y[i][rs], 1);
                y[i][rs] += __shfl_xor_sync(FULL, y[i][rs], 2);
            }

        if (tig == 0) {
            int col = w >> 2;
#pragma unroll
            for (int i = 0; i < 2; ++i)
#pragma unroll
                for (int rs = 0; rs < 2; ++rs) {
                    int row = m0 + 16 * i + 8 * rs + gid;
                    stage[col * 128 + row] = y[i][rs];
                }
        }
        __syncthreads();   // barrier C: stage ready

        if (t < 128) {
            long row = base + t;
            float s = stage[t] + stage[128 + t] + stage[256 + t]
                    + stage[384 + t] + bout[0];
            out[row] = s * (float)out_mask[row];
        }
        __syncthreads();   // barrier D: protect X/HB/stage for next tile
    }
}

// ---------------------------------------------------------------------------
extern "C" void kernel_launch(void* const* d_in, const int* in_sizes, int n_in,
                              void* d_out, int out_size) {
    const float* edges   = (const float*)d_in[0];
    const int*   in_idx  = (const int*)d_in[1];
    const int*   in_mask = (const int*)d_in[2];
    const int*   out_idx = (const int*)d_in[3];
    const int*   out_mask= (const int*)d_in[4];
    const float* W0      = (const float*)d_in[5];
    const float* b0      = (const float*)d_in[6];
    const float* W1      = (const float*)d_in[7];
    const float* b1      = (const float*)d_in[8];
    const float* Wout    = (const float*)d_in[9];
    const float* bout    = (const float*)d_in[10];
    float* out = (float*)d_out;

    cudaFuncSetAttribute(fused_kernel,
                         cudaFuncAttributeMaxDynamicSharedMemorySize,
                         SMEM_TOTAL);
    fused_kernel<<<GRID_CTAS, 512, SMEM_TOTAL>>>(
        edges, in_idx, in_mask, out_idx, out_mask,
        W0, b0, W1, b1, Wout, bout, out);
}

// round 14
// speedup vs baseline: 2.4651x; 1.0968x over previous
#include <cuda_runtime.h>
#include <cuda_bf16.h>
#include <cuda_fp16.h>
#include <math.h>
#include <stdint.h>

// Problem constants: N=200000, K_IN=8, K_OUT=4, E=800000, D=64, H=128, O=1
#define D_DIM 64
#define K_IN 8
#define K_OUT 4
#define H_DIM 128
#define TILE_M 64
#define N_TILES 12500       // 800000 rows / 64 rows per tile
#define GRID_CTAS 296       // 2 persistent CTAs per SM

// ---------------------------------------------------------------------------
// helpers
// ---------------------------------------------------------------------------
__device__ __forceinline__ uint32_t smem_u32(const void* p) {
    uint32_t a;
    asm("{ .reg .u64 t; cvta.to.shared.u64 t, %1; cvt.u32.u64 %0, t; }"
        : "=r"(a) : "l"(p));
    return a;
}

// pack two floats to f16x2: lo -> bits[15:0], hi -> bits[31:16]
__device__ __forceinline__ uint32_t f16x2_rn(float lo, float hi) {
    uint32_t r;
    asm("cvt.rn.f16x2.f32 %0, %1, %2;" : "=r"(r) : "f"(hi), "f"(lo));
    return r;
}

// convert 8 fp32 to single fp16 16B chunk
__device__ __forceinline__ uint4 cvt8h(const float* f) {
    uint4 v;
    v.x = f16x2_rn(f[0], f[1]); v.y = f16x2_rn(f[2], f[3]);
    v.z = f16x2_rn(f[4], f[5]); v.w = f16x2_rn(f[6], f[7]);
    return v;
}

#define LDMX4(r0, r1, r2, r3, addr) \
    asm volatile("ldmatrix.sync.aligned.m8n8.x4.shared.b16 {%0,%1,%2,%3}, [%4];" \
        : "=r"(r0), "=r"(r1), "=r"(r2), "=r"(r3) : "r"(addr))

#define MMAF16(c, a, b) \
    asm volatile("mma.sync.aligned.m16n8k16.row.col.f32.f16.f16.f32 " \
        "{%0,%1,%2,%3}, {%4,%5,%6,%7}, {%8,%9}, {%0,%1,%2,%3};" \
        : "+f"((c)[0]), "+f"((c)[1]), "+f"((c)[2]), "+f"((c)[3]) \
        : "r"((a)[0]), "r"((a)[1]), "r"((a)[2]), "r"((a)[3]), \
          "r"((b)[0]), "r"((b)[1]))

// ---------------------------------------------------------------------------
// SMEM layout (bytes), TWO CTAs per SM:
//   XB  @ 0      [64 m][128 k] fp16 X    (16 KB)  256B rows, XOR-16B swizzle
//   HB  @ 16384  [64 m][128 h] fp16 H    (16 KB)
//   W0  @ 32768  [128 h][128 k] fp16     (32 KB)
//   W1  @ 65536  (32 KB)
//   STG @ 98304  4 x 64 fp32 partials (1 KB)
// Total 99328 bytes per CTA -> 2 CTAs/SM.
// ---------------------------------------------------------------------------
#define XB_B    0u
#define HB_B    16384u
#define W0_B    32768u
#define W1_B    65536u
#define STG_B   98304u
#define SMEM_TOTAL 99328

__device__ __forceinline__ uint32_t swz(int row, int chunk) {
    return (uint32_t)row * 256u + (uint32_t)((chunk ^ (row & 7)) << 4);
}

// 1-pass GEMM over k=128 (A single fp16), warp tile 32m x 32n: acc += A * W
__device__ __forceinline__ void gemm_1pass(
    uint32_t AB, uint32_t WB,
    uint32_t aOff0, uint32_t aOff1, uint32_t aKey, uint32_t cbA,
    uint32_t bOff0, uint32_t bOff1, uint32_t bKey, uint32_t cbB,
    float acc[2][4][4])
{
#pragma unroll
    for (int kc = 0; kc < 8; ++kc) {
        uint32_t ca = (uint32_t)((((uint32_t)(2 * kc) + cbA) ^ aKey) << 4);
        uint32_t cb = (uint32_t)((((uint32_t)(2 * kc) + cbB) ^ bKey) << 4);
        uint32_t a0[4], a1[4], bq0[4], bq1[4];
        LDMX4(a0[0], a0[1], a0[2], a0[3], AB + aOff0 + ca);
        LDMX4(a1[0], a1[1], a1[2], a1[3], AB + aOff1 + ca);
        LDMX4(bq0[0], bq0[1], bq0[2], bq0[3], WB + bOff0 + cb);
        LDMX4(bq1[0], bq1[1], bq1[2], bq1[3], WB + bOff1 + cb);
        MMAF16(acc[0][0], a0, bq0 + 0);
        MMAF16(acc[0][1], a0, bq0 + 2);
        MMAF16(acc[0][2], a0, bq1 + 0);
        MMAF16(acc[0][3], a0, bq1 + 2);
        MMAF16(acc[1][0], a1, bq0 + 0);
        MMAF16(acc[1][1], a1, bq0 + 2);
        MMAF16(acc[1][2], a1, bq1 + 0);
        MMAF16(acc[1][3], a1, bq1 + 2);
    }
}

// ---------------------------------------------------------------------------
// Register-only attention for one node (see R12 notes). Pooled written
// directly into X pooled-half (single fp16) rows 4*nlocal..+3, cols 64..127.
// ---------------------------------------------------------------------------
__device__ __forceinline__ void attn_node(
    const float2* r, int m_l, int ln, char* smem, int nlocal)
{
    const unsigned FULL = 0xffffffffu;
    const int sel1 = (ln >> 4) & 1;
    const int sel2 = (ln >> 3) & 1;
    const int sel3 = (ln >> 2) & 1;
    const int sel4 = (ln >> 1) & 1;
    const int sel5 = ln & 1;

    float h1[32];
#pragma unroll
    for (int i = 0; i < 32; ++i) {
        const int qa = i >> 3, ka = i & 7;
        float da = r[qa].x * r[ka].x + r[qa].y * r[ka].y;
        float db = r[qa + 4].x * r[ka].x + r[qa + 4].y * r[ka].y;
        float mine  = sel1 ? db : da;
        float their = sel1 ? da : db;
        h1[i] = mine + __shfl_xor_sync(FULL, their, 16);
    }
    float h2[16];
#pragma unroll
    for (int i = 0; i < 16; ++i) {
        float mine  = sel2 ? h1[i + 16] : h1[i];
        float their = sel2 ? h1[i] : h1[i + 16];
        h2[i] = mine + __shfl_xor_sync(FULL, their, 8);
    }
    float h3[8];
#pragma unroll
    for (int i = 0; i < 8; ++i) {
        float mine  = sel3 ? h2[i + 8] : h2[i];
        float their = sel3 ? h2[i] : h2[i + 8];
        h3[i] = mine + __shfl_xor_sync(FULL, their, 4);
    }
    float h4[4];
#pragma unroll
    for (int i = 0; i < 4; ++i) {
        float mine  = sel4 ? h3[i + 4] : h3[i];
        float their = sel4 ? h3[i] : h3[i + 4];
        h4[i] = mine + __shfl_xor_sync(FULL, their, 2);
    }
    float s0, s1;
    {
        float mine0  = sel5 ? h4[2] : h4[0];
        float their0 = sel5 ? h4[0] : h4[2];
        float mine1  = sel5 ? h4[3] : h4[1];
        float their1 = sel5 ? h4[1] : h4[3];
        s0 = (mine0 + __shfl_xor_sync(FULL, their0, 1)) * 0.125f;
        s1 = (mine1 + __shfl_xor_sync(FULL, their1, 1)) * 0.125f;
    }

    const int k0 = 2 * (ln & 3);
    int mk0 = __shfl_sync(FULL, m_l, k0);
    int mk1 = __shfl_sync(FULL, m_l, k0 + 1);
    if (!mk0) s0 = -1e9f;
    if (!mk1) s1 = -1e9f;

    float mx = fmaxf(s0, s1);
    mx = fmaxf(mx, __shfl_xor_sync(FULL, mx, 1));
    mx = fmaxf(mx, __shfl_xor_sync(FULL, mx, 2));
    float e0 = __expf(s0 - mx), e1 = __expf(s1 - mx);
    float z = e0 + e1;
    z += __shfl_xor_sync(FULL, z, 1);
    z += __shfl_xor_sync(FULL, z, 2);
    float a0 = e0 / z, a1 = e1 / z;

    int mq = __shfl_sync(FULL, m_l, ln >> 2);
    float v0 = mq ? a0 : 0.f, v1 = mq ? a1 : 0.f;
#pragma unroll
    for (int o = 4; o < 32; o <<= 1) {
        v0 += __shfl_xor_sync(FULL, v0, o);
        v1 += __shfl_xor_sync(FULL, v1, o);
    }
    int cnt = __popc(__ballot_sync(FULL, m_l != 0));
    float inv_denom = 1.f / fmaxf((float)cnt, 1.f);

    float px = 0.f, py = 0.f;
#pragma unroll
    for (int k = 0; k < 8; ++k) {
        float wk = (k & 1) ? __shfl_sync(FULL, v1, k >> 1)
                           : __shfl_sync(FULL, v0, k >> 1);
        px += wk * r[k].x;
        py += wk * r[k].y;
    }
    px *= inv_denom;
    py *= inv_denom;

    uint32_t hw = f16x2_rn(px, py);
    const int chunk = 8 + (ln >> 2);
    const uint32_t cof = (uint32_t)((ln & 3) * 4);
#pragma unroll
    for (int rr = 0; rr < 4; ++rr) {
        int row = nlocal * 4 + rr;
        uint32_t off = (uint32_t)row * 256u
                     + (uint32_t)((chunk ^ (row & 7)) << 4) + cof;
        *(uint32_t*)(smem + XB_B + off) = hw;
    }
}

// ---------------------------------------------------------------------------
// Persistent fused kernel: attention + 3-layer MLP per 64-row tile.
// 296 CTAs x 256 threads (8 warps), 2 CTAs/SM, ~42 tiles each.
// ---------------------------------------------------------------------------
__global__ void __launch_bounds__(256, 2) fused_kernel(
    const float* __restrict__ edges,
    const int* __restrict__ in_idx,
    const int* __restrict__ in_mask,
    const int* __restrict__ out_idx,
    const int* __restrict__ out_mask,
    const float* __restrict__ W0,
    const float* __restrict__ b0,
    const float* __restrict__ W1,
    const float* __restrict__ b1,
    const float* __restrict__ Wout,
    const float* __restrict__ bout,
    float* __restrict__ out)
{
    extern __shared__ char smem[];
    const uint32_t sb = smem_u32(smem);
    const unsigned FULL = 0xffffffffu;

    const int t    = threadIdx.x;
    const int lane = t & 31;
    const int w    = t >> 5;        // 0..7

    // ---- load W0/W1 -> single fp16 smem, ONCE (2 threads/row, 8 chunks) ----
    {
        const int h = t & 127;
        const int q = t >> 7;       // 0..1
        const int key = h & 7;
        const float4* s0 = (const float4*)(W0 + (size_t)h * H_DIM + q * 64);
        const float4* s1 = (const float4*)(W1 + (size_t)h * H_DIM + q * 64);
#pragma unroll
        for (int c = 0; c < 8; ++c) {
            int chunk = q * 8 + c;
            uint32_t off = (uint32_t)h * 256u + (uint32_t)((chunk ^ key) << 4);
            {
                float4 f0 = s0[2 * c], f1 = s0[2 * c + 1];
                float f[8] = {f0.x, f0.y, f0.z, f0.w, f1.x, f1.y, f1.z, f1.w};
                *(uint4*)(smem + W0_B + off) = cvt8h(f);
            }
            {
                float4 f0 = s1[2 * c], f1 = s1[2 * c + 1];
                float f[8] = {f0.x, f0.y, f0.z, f0.w, f1.x, f1.y, f1.z, f1.w};
                *(uint4*)(smem + W1_B + off) = cvt8h(f);
            }
        }
    }

    // ---- per-lane GEMM geometry (warp grid 2m x 4n, warp tile 32m x 32n) ----
    const int m0  = (w & 1) * 32;
    const int n0  = (w >> 1) * 32;
    const int gid = lane >> 2;      // 0..7
    const int tig = lane & 3;       // 0..3
    const int sub = lane >> 3;      // 0..3
    const int r8  = lane & 7;
    const int aRow = m0 + (sub & 1) * 8 + r8;
    const uint32_t aOff0 = (uint32_t)aRow * 256u;
    const uint32_t aOff1 = (uint32_t)(aRow + 16) * 256u;
    const uint32_t aKey  = (uint32_t)r8;
    const uint32_t cbA   = (uint32_t)(sub >> 1);
    const int bRow = n0 + (sub >> 1) * 8 + r8;
    const uint32_t bOff0 = (uint32_t)bRow * 256u;
    const uint32_t bOff1 = (uint32_t)(bRow + 16) * 256u;
    const uint32_t bKey  = (uint32_t)r8;
    const uint32_t cbB   = (uint32_t)(sub & 1);

    float* stage = (float*)(smem + STG_B);

    // X-fill roles: 4 threads per row (t>>6 selects k-quarter), 2 chunks each
    const int xrow = t & 63;
    const int xq   = t >> 6;        // 0..3

    for (int tile = blockIdx.x; tile < N_TILES; tile += gridDim.x) {
        const long base = (long)tile * TILE_M;

        // ============ attention: 2 nodes per warp, register-only ============
        {
            const int nodeA = tile * 16 + w * 2;
            const int nodeB = nodeA + 1;

            int idxA = 0, mA = 0, idxB = 0, mB = 0;
            if (lane < K_IN) {
                idxA = in_idx[(size_t)nodeA * K_IN + lane];
                mA   = in_mask[(size_t)nodeA * K_IN + lane];
                idxB = in_idx[(size_t)nodeB * K_IN + lane];
                mB   = in_mask[(size_t)nodeB * K_IN + lane];
            }

            float2 rA[K_IN], rB[K_IN];
#pragma unroll
            for (int k = 0; k < K_IN; ++k) {
                int ek = __shfl_sync(FULL, idxA, k);
                rA[k] = *(const float2*)(edges + (size_t)ek * D_DIM + lane * 2);
            }
#pragma unroll
            for (int k = 0; k < K_IN; ++k) {
                int ek = __shfl_sync(FULL, idxB, k);
                rB[k] = *(const float2*)(edges + (size_t)ek * D_DIM + lane * 2);
            }
            attn_node(rA, mA, lane, smem, w * 2);
            attn_node(rB, mB, lane, smem, w * 2 + 1);
        }

        // ---- edge-half X fill: all 256 threads, 2 chunks each ----
        {
            long grow = base + xrow;
            int eidx = out_idx[grow];
            const float4* s4 = (const float4*)(edges + (size_t)eidx * D_DIM
                                               + xq * 16);
#pragma unroll
            for (int c = 0; c < 2; ++c) {
                float4 f0 = s4[2 * c], f1 = s4[2 * c + 1];
                float f[8] = {f0.x, f0.y, f0.z, f0.w, f1.x, f1.y, f1.z, f1.w};
                uint32_t off = swz(xrow, 2 * xq + c);
                *(uint4*)(smem + XB_B + off) = cvt8h(f);
            }
        }
        __syncthreads();   // barrier A: X fully ready (W visible on iter 0)

        // ============ GEMM layer 1 (1-pass, A = XB) ============
        float acc[2][4][4];
#pragma unroll
        for (int i = 0; i < 2; ++i)
#pragma unroll
            for (int j = 0; j < 4; ++j)
#pragma unroll
                for (int p = 0; p < 4; ++p) acc[i][j][p] = 0.f;

        gemm_1pass(sb + XB_B, sb + W0_B,
                   aOff0, aOff1, aKey, cbA, bOff0, bOff1, bKey, cbB, acc);

        // ---- epilogue 1: H = relu(acc + b0) -> HB (single fp16) ----
#pragma unroll
        for (int j = 0; j < 4; ++j) {
            int h0 = n0 + 8 * j + 2 * tig;
            float2 bb = *(const float2*)(b0 + h0);
            int chunk = (n0 + 8 * j) >> 3;
            uint32_t cof = (uint32_t)(tig * 4);
#pragma unroll
            for (int i = 0; i < 2; ++i) {
#pragma unroll
                for (int rs = 0; rs < 2; ++rs) {
                    int row = m0 + 16 * i + 8 * rs + gid;
                    float v0 = fmaxf(acc[i][j][2 * rs]     + bb.x, 0.f);
                    float v1 = fmaxf(acc[i][j][2 * rs + 1] + bb.y, 0.f);
                    uint32_t hw = f16x2_rn(v0, v1);
                    uint32_t off = (uint32_t)row * 256u
                                 + (uint32_t)((chunk ^ (row & 7)) << 4) + cof;
                    *(uint32_t*)(smem + HB_B + off) = hw;
                }
            }
        }
        __syncthreads();   // barrier B: HB ready

        // ============ GEMM layer 2 (1-pass, A = HB) ============
#pragma unroll
        for (int i = 0; i < 2; ++i)
#pragma unroll
            for (int j = 0; j < 4; ++j)
#pragma unroll
                for (int p = 0; p < 4; ++p) acc[i][j][p] = 0.f;

        gemm_1pass(sb + HB_B, sb + W1_B,
                   aOff0, aOff1, aKey, cbA, bOff0, bOff1, bKey, cbB, acc);

        // ---- final epilogue: relu(+b1), dot Wout, reduce ----
        float y[2][2] = {{0.f, 0.f}, {0.f, 0.f}};
#pragma unroll
        for (int j = 0; j < 4; ++j) {
            int h0 = n0 + 8 * j + 2 * tig;
            float2 bb = *(const float2*)(b1 + h0);
            float2 ww = *(const float2*)(Wout + h0);
#pragma unroll
            for (int i = 0; i < 2; ++i) {
#pragma unroll
                for (int rs = 0; rs < 2; ++rs) {
                    float v0 = fmaxf(acc[i][j][2 * rs]     + bb.x, 0.f);
                    float v1 = fmaxf(acc[i][j][2 * rs + 1] + bb.y, 0.f);
                    y[i][rs] += ww.x * v0 + ww.y * v1;
                }
            }
        }
#pragma unroll
        for (int i = 0; i < 2; ++i)
#pragma unroll
            for (int rs = 0; rs < 2; ++rs) {
                y[i][rs] += __shfl_xor_sync(FULL, y[i][rs], 1);
                y[i][rs] += __shfl_xor_sync(FULL, y[i][rs], 2);
            }

        if (tig == 0) {
            int col = w >> 1;
#pragma unroll
            for (int i = 0; i < 2; ++i)
#pragma unroll
                for (int rs = 0; rs < 2; ++rs) {
                    int row = m0 + 16 * i + 8 * rs + gid;
                    stage[col * TILE_M + row] = y[i][rs];
                }
        }
        __syncthreads();   // barrier C: stage ready

        if (t < TILE_M) {
            long row = base + t;
            float s = stage[t] + stage[64 + t] + stage[128 + t]
                    + stage[192 + t] + bout[0];
            out[row] = s * (float)out_mask[row];
        }
        __syncthreads();   // barrier D: protect X/HB/stage for next tile
    }
}

// ---------------------------------------------------------------------------
extern "C" void kernel_launch(void* const* d_in, const int* in_sizes, int n_in,
                              void* d_out, int out_size) {
    const float* edges   = (const float*)d_in[0];
    const int*   in_idx  = (const int*)d_in[1];
    const int*   in_mask = (const int*)d_in[2];
    const int*   out_idx = (const int*)d_in[3];
    const int*   out_mask= (const int*)d_in[4];
    const float* W0      = (const float*)d_in[5];
    const float* b0      = (const float*)d_in[6];
    const float* W1      = (const float*)d_in[7];
    const float* b1      = (const float*)d_in[8];
    const float* Wout    = (const float*)d_in[9];
    const float* bout    = (const float*)d_in[10];
    float* out = (float*)d_out;

    cudaFuncSetAttribute(fused_kernel,
                         cudaFuncAttributeMaxDynamicSharedMemorySize,
                         SMEM_TOTAL);
    fused_kernel<<<GRID_CTAS, 256, SMEM_TOTAL>>>(
        edges, in_idx, in_mask, out_idx, out_mask,
        W0, b0, W1, b1, Wout, bout, out);
}

// round 15
// speedup vs baseline: 2.7649x; 1.1216x over previous
#include <cuda_runtime.h>
#include <cuda_bf16.h>
#include <cuda_fp16.h>
#include <math.h>
#include <stdint.h>

// Problem constants: N=200000, K_IN=8, K_OUT=4, E=800000, D=64, H=128, O=1
#define D_DIM 64
#define K_IN 8
#define K_OUT 4
#define H_DIM 128
#define TILE_M 64
#define N_TILES 12500       // 800000 rows / 64 rows per tile
#define GRID_CTAS 296       // 2 persistent CTAs per SM

// ---------------------------------------------------------------------------
// helpers
// ---------------------------------------------------------------------------
__device__ __forceinline__ uint32_t smem_u32(const void* p) {
    uint32_t a;
    asm("{ .reg .u64 t; cvta.to.shared.u64 t, %1; cvt.u32.u64 %0, t; }"
        : "=r"(a) : "l"(p));
    return a;
}

// pack two floats to f16x2: lo -> bits[15:0], hi -> bits[31:16]
__device__ __forceinline__ uint32_t f16x2_rn(float lo, float hi) {
    uint32_t r;
    asm("cvt.rn.f16x2.f32 %0, %1, %2;" : "=r"(r) : "f"(hi), "f"(lo));
    return r;
}

// convert 8 fp32 to single fp16 16B chunk
__device__ __forceinline__ uint4 cvt8h(const float* f) {
    uint4 v;
    v.x = f16x2_rn(f[0], f[1]); v.y = f16x2_rn(f[2], f[3]);
    v.z = f16x2_rn(f[4], f[5]); v.w = f16x2_rn(f[6], f[7]);
    return v;
}

#define LDMX4(r0, r1, r2, r3, addr) \
    asm volatile("ldmatrix.sync.aligned.m8n8.x4.shared.b16 {%0,%1,%2,%3}, [%4];" \
        : "=r"(r0), "=r"(r1), "=r"(r2), "=r"(r3) : "r"(addr))

#define MMAF16(c, a, b) \
    asm volatile("mma.sync.aligned.m16n8k16.row.col.f32.f16.f16.f32 " \
        "{%0,%1,%2,%3}, {%4,%5,%6,%7}, {%8,%9}, {%0,%1,%2,%3};" \
        : "+f"((c)[0]), "+f"((c)[1]), "+f"((c)[2]), "+f"((c)[3]) \
        : "r"((a)[0]), "r"((a)[1]), "r"((a)[2]), "r"((a)[3]), \
          "r"((b)[0]), "r"((b)[1]))

// ---------------------------------------------------------------------------
// SMEM layout (bytes), TWO CTAs per SM:
//   XB  @ 0      [64 m][128 k] fp16 X    (16 KB)  256B rows, XOR-16B swizzle
//   HB  @ 16384  [64 m][128 h] fp16 H    (16 KB)
//   W0  @ 32768  [128 h][128 k] fp16     (32 KB)
//   W1  @ 65536  (32 KB)
//   STG @ 98304  4 x 64 fp32 partials (1 KB)
// Total 99328 bytes per CTA -> 2 CTAs/SM.
// ---------------------------------------------------------------------------
#define XB_B    0u
#define HB_B    16384u
#define W0_B    32768u
#define W1_B    65536u
#define STG_B   98304u
#define SMEM_TOTAL 99328

__device__ __forceinline__ uint32_t swz(int row, int chunk) {
    return (uint32_t)row * 256u + (uint32_t)((chunk ^ (row & 7)) << 4);
}

// 1-pass GEMM over k=128 (A single fp16), warp tile 32m x 32n: acc += A * W
__device__ __forceinline__ void gemm_1pass(
    uint32_t AB, uint32_t WB,
    uint32_t aOff0, uint32_t aOff1, uint32_t aKey, uint32_t cbA,
    uint32_t bOff0, uint32_t bOff1, uint32_t bKey, uint32_t cbB,
    float acc[2][4][4])
{
#pragma unroll
    for (int kc = 0; kc < 8; ++kc) {
        uint32_t ca = (uint32_t)((((uint32_t)(2 * kc) + cbA) ^ aKey) << 4);
        uint32_t cb = (uint32_t)((((uint32_t)(2 * kc) + cbB) ^ bKey) << 4);
        uint32_t a0[4], a1[4], bq0[4], bq1[4];
        LDMX4(a0[0], a0[1], a0[2], a0[3], AB + aOff0 + ca);
        LDMX4(a1[0], a1[1], a1[2], a1[3], AB + aOff1 + ca);
        LDMX4(bq0[0], bq0[1], bq0[2], bq0[3], WB + bOff0 + cb);
        LDMX4(bq1[0], bq1[1], bq1[2], bq1[3], WB + bOff1 + cb);
        MMAF16(acc[0][0], a0, bq0 + 0);
        MMAF16(acc[0][1], a0, bq0 + 2);
        MMAF16(acc[0][2], a0, bq1 + 0);
        MMAF16(acc[0][3], a0, bq1 + 2);
        MMAF16(acc[1][0], a1, bq0 + 0);
        MMAF16(acc[1][1], a1, bq0 + 2);
        MMAF16(acc[1][2], a1, bq1 + 0);
        MMAF16(acc[1][3], a1, bq1 + 2);
    }
}

// ---------------------------------------------------------------------------
// Register-only attention for one node (see R12 notes). Pooled written
// directly into X pooled-half (single fp16) rows 4*nlocal..+3, cols 64..127.
// ---------------------------------------------------------------------------
__device__ __forceinline__ void attn_node(
    const float2* r, int m_l, int ln, char* smem, int nlocal)
{
    const unsigned FULL = 0xffffffffu;
    const int sel1 = (ln >> 4) & 1;
    const int sel2 = (ln >> 3) & 1;
    const int sel3 = (ln >> 2) & 1;
    const int sel4 = (ln >> 1) & 1;
    const int sel5 = ln & 1;

    float h1[32];
#pragma unroll
    for (int i = 0; i < 32; ++i) {
        const int qa = i >> 3, ka = i & 7;
        float da = r[qa].x * r[ka].x + r[qa].y * r[ka].y;
        float db = r[qa + 4].x * r[ka].x + r[qa + 4].y * r[ka].y;
        float mine  = sel1 ? db : da;
        float their = sel1 ? da : db;
        h1[i] = mine + __shfl_xor_sync(FULL, their, 16);
    }
    float h2[16];
#pragma unroll
    for (int i = 0; i < 16; ++i) {
        float mine  = sel2 ? h1[i + 16] : h1[i];
        float their = sel2 ? h1[i] : h1[i + 16];
        h2[i] = mine + __shfl_xor_sync(FULL, their, 8);
    }
    float h3[8];
#pragma unroll
    for (int i = 0; i < 8; ++i) {
        float mine  = sel3 ? h2[i + 8] : h2[i];
        float their = sel3 ? h2[i] : h2[i + 8];
        h3[i] = mine + __shfl_xor_sync(FULL, their, 4);
    }
    float h4[4];
#pragma unroll
    for (int i = 0; i < 4; ++i) {
        float mine  = sel4 ? h3[i + 4] : h3[i];
        float their = sel4 ? h3[i] : h3[i + 4];
        h4[i] = mine + __shfl_xor_sync(FULL, their, 2);
    }
    float s0, s1;
    {
        float mine0  = sel5 ? h4[2] : h4[0];
        float their0 = sel5 ? h4[0] : h4[2];
        float mine1  = sel5 ? h4[3] : h4[1];
        float their1 = sel5 ? h4[1] : h4[3];
        s0 = (mine0 + __shfl_xor_sync(FULL, their0, 1)) * 0.125f;
        s1 = (mine1 + __shfl_xor_sync(FULL, their1, 1)) * 0.125f;
    }

    const int k0 = 2 * (ln & 3);
    int mk0 = __shfl_sync(FULL, m_l, k0);
    int mk1 = __shfl_sync(FULL, m_l, k0 + 1);
    if (!mk0) s0 = -1e9f;
    if (!mk1) s1 = -1e9f;

    float mx = fmaxf(s0, s1);
    mx = fmaxf(mx, __shfl_xor_sync(FULL, mx, 1));
    mx = fmaxf(mx, __shfl_xor_sync(FULL, mx, 2));
    float e0 = __expf(s0 - mx), e1 = __expf(s1 - mx);
    float z = e0 + e1;
    z += __shfl_xor_sync(FULL, z, 1);
    z += __shfl_xor_sync(FULL, z, 2);
    float a0 = e0 / z, a1 = e1 / z;

    int mq = __shfl_sync(FULL, m_l, ln >> 2);
    float v0 = mq ? a0 : 0.f, v1 = mq ? a1 : 0.f;
#pragma unroll
    for (int o = 4; o < 32; o <<= 1) {
        v0 += __shfl_xor_sync(FULL, v0, o);
        v1 += __shfl_xor_sync(FULL, v1, o);
    }
    int cnt = __popc(__ballot_sync(FULL, m_l != 0));
    float inv_denom = 1.f / fmaxf((float)cnt, 1.f);

    float px = 0.f, py = 0.f;
#pragma unroll
    for (int k = 0; k < 8; ++k) {
        float wk = (k & 1) ? __shfl_sync(FULL, v1, k >> 1)
                           : __shfl_sync(FULL, v0, k >> 1);
        px += wk * r[k].x;
        py += wk * r[k].y;
    }
    px *= inv_denom;
    py *= inv_denom;

    uint32_t hw = f16x2_rn(px, py);
    const int chunk = 8 + (ln >> 2);
    const uint32_t cof = (uint32_t)((ln & 3) * 4);
#pragma unroll
    for (int rr = 0; rr < 4; ++rr) {
        int row = nlocal * 4 + rr;
        uint32_t off = (uint32_t)row * 256u
                     + (uint32_t)((chunk ^ (row & 7)) << 4) + cof;
        *(uint32_t*)(smem + XB_B + off) = hw;
    }
}

// ---------------------------------------------------------------------------
// attention (2 nodes/warp) + edge-half X fill, with prefetched indices.
// ---------------------------------------------------------------------------
__device__ __forceinline__ void attn_and_fill(
    const float* __restrict__ edges, char* smem,
    int idxA, int mA, int idxB, int mB, int eidx,
    int lane, int w, int xrow, int xq)
{
    const unsigned FULL = 0xffffffffu;
    float2 rA[K_IN], rB[K_IN];
#pragma unroll
    for (int k = 0; k < K_IN; ++k) {
        int ek = __shfl_sync(FULL, idxA, k);
        rA[k] = *(const float2*)(edges + (size_t)ek * D_DIM + lane * 2);
    }
#pragma unroll
    for (int k = 0; k < K_IN; ++k) {
        int ek = __shfl_sync(FULL, idxB, k);
        rB[k] = *(const float2*)(edges + (size_t)ek * D_DIM + lane * 2);
    }
    // edge-half X fill (independent of attention math; loads issued here too)
    {
        const float4* s4 = (const float4*)(edges + (size_t)eidx * D_DIM
                                           + xq * 16);
        float4 f0a = s4[0], f1a = s4[1], f0b = s4[2], f1b = s4[3];
        float fa[8] = {f0a.x, f0a.y, f0a.z, f0a.w, f1a.x, f1a.y, f1a.z, f1a.w};
        float fb[8] = {f0b.x, f0b.y, f0b.z, f0b.w, f1b.x, f1b.y, f1b.z, f1b.w};
        *(uint4*)(smem + XB_B + swz(xrow, 2 * xq))     = cvt8h(fa);
        *(uint4*)(smem + XB_B + swz(xrow, 2 * xq + 1)) = cvt8h(fb);
    }
    attn_node(rA, mA, lane, smem, w * 2);
    attn_node(rB, mB, lane, smem, w * 2 + 1);
}

// ---------------------------------------------------------------------------
// Persistent fused kernel, software-pipelined:
//   prologue: attn+fill(tile0); barrier
//   loop: prefetch idx(next); GEMM1; epi1; B; attn+fill(next); GEMM2; epi2;
//         stage; C; out
// 2 barriers per tile.
// ---------------------------------------------------------------------------
__global__ void __launch_bounds__(256, 2) fused_kernel(
    const float* __restrict__ edges,
    const int* __restrict__ in_idx,
    const int* __restrict__ in_mask,
    const int* __restrict__ out_idx,
    const int* __restrict__ out_mask,
    const float* __restrict__ W0,
    const float* __restrict__ b0,
    const float* __restrict__ W1,
    const float* __restrict__ b1,
    const float* __restrict__ Wout,
    const float* __restrict__ bout,
    float* __restrict__ out)
{
    extern __shared__ char smem[];
    const uint32_t sb = smem_u32(smem);
    const unsigned FULL = 0xffffffffu;

    const int t    = threadIdx.x;
    const int lane = t & 31;
    const int w    = t >> 5;        // 0..7

    // ---- load W0/W1 -> single fp16 smem, ONCE ----
    {
        const int h = t & 127;
        const int q = t >> 7;       // 0..1
        const int key = h & 7;
        const float4* s0 = (const float4*)(W0 + (size_t)h * H_DIM + q * 64);
        const float4* s1 = (const float4*)(W1 + (size_t)h * H_DIM + q * 64);
#pragma unroll
        for (int c = 0; c < 8; ++c) {
            int chunk = q * 8 + c;
            uint32_t off = (uint32_t)h * 256u + (uint32_t)((chunk ^ key) << 4);
            {
                float4 f0 = s0[2 * c], f1 = s0[2 * c + 1];
                float f[8] = {f0.x, f0.y, f0.z, f0.w, f1.x, f1.y, f1.z, f1.w};
                *(uint4*)(smem + W0_B + off) = cvt8h(f);
            }
            {
                float4 f0 = s1[2 * c], f1 = s1[2 * c + 1];
                float f[8] = {f0.x, f0.y, f0.z, f0.w, f1.x, f1.y, f1.z, f1.w};
                *(uint4*)(smem + W1_B + off) = cvt8h(f);
            }
        }
    }

    // ---- per-lane GEMM geometry (warp grid 2m x 4n, warp tile 32m x 32n) ----
    const int m0  = (w & 1) * 32;
    const int n0  = (w >> 1) * 32;
    const int gid = lane >> 2;      // 0..7
    const int tig = lane & 3;       // 0..3
    const int sub = lane >> 3;      // 0..3
    const int r8  = lane & 7;
    const int aRow = m0 + (sub & 1) * 8 + r8;
    const uint32_t aOff0 = (uint32_t)aRow * 256u;
    const uint32_t aOff1 = (uint32_t)(aRow + 16) * 256u;
    const uint32_t aKey  = (uint32_t)r8;
    const uint32_t cbA   = (uint32_t)(sub >> 1);
    const int bRow = n0 + (sub >> 1) * 8 + r8;
    const uint32_t bOff0 = (uint32_t)bRow * 256u;
    const uint32_t bOff1 = (uint32_t)(bRow + 16) * 256u;
    const uint32_t bKey  = (uint32_t)r8;
    const uint32_t cbB   = (uint32_t)(sub & 1);

    float* stage = (float*)(smem + STG_B);

    // X-fill roles: 4 threads per row, 16 k each
    const int xrow = t & 63;
    const int xq   = t >> 6;        // 0..3

    // ---- prologue: first tile's attention + X fill ----
    int tile = blockIdx.x;
    {
        const int nodeA = tile * 16 + w * 2;
        int idxA = 0, mA = 0, idxB = 0, mB = 0;
        if (lane < K_IN) {
            idxA = in_idx[(size_t)nodeA * K_IN + lane];
            mA   = in_mask[(size_t)nodeA * K_IN + lane];
            idxB = in_idx[(size_t)(nodeA + 1) * K_IN + lane];
            mB   = in_mask[(size_t)(nodeA + 1) * K_IN + lane];
        }
        int eidx = out_idx[(size_t)tile * TILE_M + xrow];
        attn_and_fill(edges, smem, idxA, mA, idxB, mB, eidx,
                      lane, w, xrow, xq);
    }
    __syncthreads();   // X + W ready

    for (; tile < N_TILES; tile += gridDim.x) {
        const long base = (long)tile * TILE_M;
        const int next = tile + (int)gridDim.x;
        const bool hasNext = (next < N_TILES);

        // ---- prefetch next-tile indices (latency hides under GEMM1) ----
        int nIdxA = 0, nMA = 0, nIdxB = 0, nMB = 0, nEidx = 0;
        if (hasNext) {
            const int nodeA = next * 16 + w * 2;
            if (lane < K_IN) {
                nIdxA = in_idx[(size_t)nodeA * K_IN + lane];
                nMA   = in_mask[(size_t)nodeA * K_IN + lane];
                nIdxB = in_idx[(size_t)(nodeA + 1) * K_IN + lane];
                nMB   = in_mask[(size_t)(nodeA + 1) * K_IN + lane];
            }
            nEidx = out_idx[(size_t)next * TILE_M + xrow];
        }

        // ============ GEMM layer 1 (A = XB) ============
        float acc[2][4][4];
#pragma unroll
        for (int i = 0; i < 2; ++i)
#pragma unroll
            for (int j = 0; j < 4; ++j)
#pragma unroll
                for (int p = 0; p < 4; ++p) acc[i][j][p] = 0.f;

        gemm_1pass(sb + XB_B, sb + W0_B,
                   aOff0, aOff1, aKey, cbA, bOff0, bOff1, bKey, cbB, acc);

        // ---- epilogue 1: H = relu(acc + b0) -> HB ----
#pragma unroll
        for (int j = 0; j < 4; ++j) {
            int h0 = n0 + 8 * j + 2 * tig;
            float2 bb = *(const float2*)(b0 + h0);
            int chunk = (n0 + 8 * j) >> 3;
            uint32_t cof = (uint32_t)(tig * 4);
#pragma unroll
            for (int i = 0; i < 2; ++i) {
#pragma unroll
                for (int rs = 0; rs < 2; ++rs) {
                    int row = m0 + 16 * i + 8 * rs + gid;
                    float v0 = fmaxf(acc[i][j][2 * rs]     + bb.x, 0.f);
                    float v1 = fmaxf(acc[i][j][2 * rs + 1] + bb.y, 0.f);
                    uint32_t hw = f16x2_rn(v0, v1);
                    uint32_t off = (uint32_t)row * 256u
                                 + (uint32_t)((chunk ^ (row & 7)) << 4) + cof;
                    *(uint32_t*)(smem + HB_B + off) = hw;
                }
            }
        }
        __syncthreads();   // barrier B: HB ready; XB reads complete (XB dead)

        // ---- next tile's attention + X fill into (dead) XB ----
        if (hasNext) {
            attn_and_fill(edges, smem, nIdxA, nMA, nIdxB, nMB, nEidx,
                          lane, w, xrow, xq);
        }

        // ============ GEMM layer 2 (A = HB) ============
#pragma unroll
        for (int i = 0; i < 2; ++i)
#pragma unroll
            for (int j = 0; j < 4; ++j)
#pragma unroll
                for (int p = 0; p < 4; ++p) acc[i][j][p] = 0.f;

        gemm_1pass(sb + HB_B, sb + W1_B,
                   aOff0, aOff1, aKey, cbA, bOff0, bOff1, bKey, cbB, acc);

        // ---- final epilogue: relu(+b1), dot Wout, reduce ----
        float y[2][2] = {{0.f, 0.f}, {0.f, 0.f}};
#pragma unroll
        for (int j = 0; j < 4; ++j) {
            int h0 = n0 + 8 * j + 2 * tig;
            float2 bb = *(const float2*)(b1 + h0);
            float2 ww = *(const float2*)(Wout + h0);
#pragma unroll
            for (int i = 0; i < 2; ++i) {
#pragma unroll
                for (int rs = 0; rs < 2; ++rs) {
                    float v0 = fmaxf(acc[i][j][2 * rs]     + bb.x, 0.f);
                    float v1 = fmaxf(acc[i][j][2 * rs + 1] + bb.y, 0.f);
                    y[i][rs] += ww.x * v0 + ww.y * v1;
                }
            }
        }
#pragma unroll
        for (int i = 0; i < 2; ++i)
#pragma unroll
            for (int rs = 0; rs < 2; ++rs) {
                y[i][rs] += __shfl_xor_sync(FULL, y[i][rs], 1);
                y[i][rs] += __shfl_xor_sync(FULL, y[i][rs], 2);
            }

        if (tig == 0) {
            int col = w >> 1;
#pragma unroll
            for (int i = 0; i < 2; ++i)
#pragma unroll
                for (int rs = 0; rs < 2; ++rs) {
                    int row = m0 + 16 * i + 8 * rs + gid;
                    stage[col * TILE_M + row] = y[i][rs];
                }
        }
        __syncthreads();   // barrier C: stage ready; XB writes complete

        if (t < TILE_M) {
            long row = base + t;
            float s = stage[t] + stage[64 + t] + stage[128 + t]
                    + stage[192 + t] + bout[0];
            out[row] = s * (float)out_mask[row];
        }
        // no barrier D: next-iter stage writes are ordered after barrier B'
        // (every thread's out-read precedes its B' arrival), and next-iter
        // GEMM1's XB reads are ordered after barrier C above.
    }
}

// ---------------------------------------------------------------------------
extern "C" void kernel_launch(void* const* d_in, const int* in_sizes, int n_in,
                              void* d_out, int out_size) {
    const float* edges   = (const float*)d_in[0];
    const int*   in_idx  = (const int*)d_in[1];
    const int*   in_mask = (const int*)d_in[2];
    const int*   out_idx = (const int*)d_in[3];
    const int*   out_mask= (const int*)d_in[4];
    const float* W0      = (const float*)d_in[5];
    const float* b0      = (const float*)d_in[6];
    const float* W1      = (const float*)d_in[7];
    const float* b1      = (const float*)d_in[8];
    const float* Wout    = (const float*)d_in[9];
    const float* bout    = (const float*)d_in[10];
    float* out = (float*)d_out;

    cudaFuncSetAttribute(fused_kernel,
                         cudaFuncAttributeMaxDynamicSharedMemorySize,
                         SMEM_TOTAL);
    fused_kernel<<<GRID_CTAS, 256, SMEM_TOTAL>>>(
        edges, in_idx, in_mask, out_idx, out_mask,
        W0, b0, W1, b1, Wout, bout, out);
}